// round 14
// baseline (speedup 1.0000x reference)
#include <cuda_runtime.h>
#include <cstdint>

#define NN 50000
#define NP 50048      // padded node stride for transposed tensors
#define DD 128
#define HH 128
#define CC 40
#define LL 3
#define EE 800000
#define LSTR 40       // padded SMEM row stride in bf16 units (80 bytes)
#define NREP 16       // BN stat replica buffers

// mega-kernel block ranges
#define DEC_B 3125            // decode blocks (EE/256)
#define TX_B  1563            // tx blocks (NN/32)
#define PWB_B 320             // prepWB(0) blocks (640*128/256)
#define PWO_B 400             // prepWO blocks (2560*40/256)

// ------------------- device scratch (static: no allocation) -------------------
__device__ int    g_src[EE];
__device__ int    g_dst[EE];
__device__ float  g_dis[NN];
__device__ int    g_cnt[NN];
__device__ int    g_off[NN + 1];
__device__ int    g_fill[NN];
__device__ int    g_csr[EE];
__device__ int    g_bsum[256];
__device__ int    g_boff[256];
__device__ float  g_XT[(size_t)512 * NP];    // transposed raw values [d][n]
__device__ float  g_mu[4][NP];               // per-LN-set node mean
__device__ float  g_rs[4][NP];               // per-LN-set node rstd
__device__ float  g_osum[NP];                // output-LN partial: sum over 512 dims
__device__ float  g_osq[NP];                 // output-LN partial: sumsq
__device__ float  g_h1[(size_t)NN * HH];     // pre-scaled by dis[row]
__device__ float  g_h2[(size_t)NN * HH];
__device__ unsigned short g_WBh[20 * 128 * 32];   // layer B bf16-hi [chunk][n][k]
__device__ unsigned short g_WBl[20 * 128 * 32];
__device__ unsigned short g_WOh[80 * 40 * 32];    // output B bf16-hi [chunk][n][k]
__device__ unsigned short g_WOl[80 * 40 * 32];
__device__ float  g_sumf[LL][NREP][HH];      // per-layer BN column sums (replicated)
__device__ float  g_sqf[LL][NREP][HH];       // per-layer BN column sumsq

// ------------------- helpers -------------------
__device__ __forceinline__ uint32_t smem_u32(const void* p) {
    uint32_t a;
    asm("{ .reg .u64 t; cvta.to.shared.u64 t, %1; cvt.u32.u64 %0, t; }" : "=r"(a) : "l"(p));
    return a;
}
__device__ __forceinline__ uint32_t pkbf(float a, float b) {   // [bf16(a) lo16 | bf16(b) hi16]
    uint32_t r;
    asm("cvt.rn.bf16x2.f32 %0, %1, %2;" : "=r"(r) : "f"(b), "f"(a));
    return r;
}
__device__ __forceinline__ float lo2f(uint32_t v) { return __uint_as_float(v << 16); }
__device__ __forceinline__ float hi2f(uint32_t v) { return __uint_as_float(v & 0xffff0000u); }

__device__ __forceinline__ void ldsm4(uint32_t& r0, uint32_t& r1, uint32_t& r2, uint32_t& r3,
                                      uint32_t a) {
    asm volatile("ldmatrix.sync.aligned.m8n8.x4.shared.b16 {%0,%1,%2,%3}, [%4];"
                 : "=r"(r0), "=r"(r1), "=r"(r2), "=r"(r3) : "r"(a));
}
__device__ __forceinline__ void ldsm2(uint32_t& r0, uint32_t& r1, uint32_t a) {
    asm volatile("ldmatrix.sync.aligned.m8n8.x2.shared.b16 {%0,%1}, [%2];"
                 : "=r"(r0), "=r"(r1) : "r"(a));
}
__device__ __forceinline__ void mmabf(float* c, const uint32_t* a, uint32_t b0, uint32_t b1) {
    asm volatile("mma.sync.aligned.m16n8k16.row.col.f32.bf16.bf16.f32 "
                 "{%0,%1,%2,%3}, {%4,%5,%6,%7}, {%8,%9}, {%0,%1,%2,%3};"
                 : "+f"(c[0]), "+f"(c[1]), "+f"(c[2]), "+f"(c[3])
                 : "r"(a[0]), "r"(a[1]), "r"(a[2]), "r"(a[3]), "r"(b0), "r"(b1));
}
__device__ __forceinline__ void hilo2(float v0, float v1, uint32_t& h, uint32_t& l) {
    h = pkbf(v0, v1);
    l = pkbf(v0 - lo2f(h), v1 - hi2f(h));
}
__device__ __forceinline__ float silu_f(float v) {
    return __fdividef(v, 1.0f + __expf(-v));
}
__device__ __forceinline__ void bfsplit(float v, unsigned short& h, unsigned short& l) {
    asm("cvt.rn.bf16.f32 %0, %1;" : "=h"(h) : "f"(v));
    float vl = v - __uint_as_float(((uint32_t)h) << 16);
    asm("cvt.rn.bf16.f32 %0, %1;" : "=h"(l) : "f"(vl));
}

// ------------------- zero counters + per-layer BN stats -------------------
__global__ void k_zero_cnt() {
    int i = blockIdx.x * blockDim.x + threadIdx.x;
    if (i < NN) { g_cnt[i] = 0; g_fill[i] = 0; }
    if (i < LL * NREP * HH) {
        ((float*)g_sumf)[i] = 0.f;
        ((float*)g_sqf)[i]  = 0.f;
    }
}

// ------------------- MEGA init kernel: decode | tx | prepWB(0) | prepWO -------------------
__global__ void __launch_bounds__(256) k_mega(const void* ep, const float* __restrict__ x,
                                              const float* __restrict__ sw,
                                              const float* __restrict__ bw,
                                              const float* __restrict__ swo,
                                              const float* __restrict__ bwo) {
    int b = blockIdx.x, t = threadIdx.x;
    if (b < DEC_B) {
        // ---- edge decode + degree histogram (dtype self-detected per block) ----
        __shared__ int sflag;
        if (t == 0) {
            const unsigned* e = (const unsigned*)ep;
            int z = 0;
            #pragma unroll
            for (int i = 0; i < 16; i++) z += (e[2 * i + 1] == 0u) ? 1 : 0;
            sflag = (z == 16) ? 1 : 0;
        }
        __syncthreads();
        int i = b * 256 + t;
        if (i < EE) {
            int s, d;
            if (sflag) {
                const long long* e = (const long long*)ep;
                s = (int)e[i];
                d = (int)e[EE + i];
            } else {
                const int* e = (const int*)ep;
                s = e[i];
                d = e[EE + i];
            }
            g_src[i] = s;
            g_dst[i] = d;
            atomicAdd(&g_cnt[d], 1);
        }
    } else if (b < DEC_B + TX_B) {
        // ---- x transpose + LN0 stats + output-LN partial init ----
        __shared__ float xs[32][129];
        int warp = t >> 5, lane = t & 31;
        int base = (b - DEC_B) * 32;
        #pragma unroll
        for (int rr = 0; rr < 4; rr++) {
            int r = warp * 4 + rr;
            int gr = base + r;
            if (gr < NN) {
                float v[4];
                float s = 0.f, sq = 0.f;
                #pragma unroll
                for (int j = 0; j < 4; j++) {
                    v[j] = x[(size_t)gr * DD + lane + j * 32];
                    s += v[j]; sq += v[j] * v[j];
                }
                #pragma unroll
                for (int o = 16; o; o >>= 1) {
                    s  += __shfl_xor_sync(0xffffffffu, s, o);
                    sq += __shfl_xor_sync(0xffffffffu, sq, o);
                }
                #pragma unroll
                for (int j = 0; j < 4; j++) xs[r][lane + j * 32] = v[j];
                if (lane == 0) {
                    float mean = s * (1.0f / 128.0f);
                    float var = sq * (1.0f / 128.0f) - mean * mean;
                    g_mu[0][gr] = mean;
                    g_rs[0][gr] = rsqrtf(var + 1e-5f);
                    g_osum[gr] = s;
                    g_osq[gr]  = sq;
                }
            }
        }
        __syncthreads();
        #pragma unroll 4
        for (int idx = t; idx < 32 * 128; idx += 256) {
            int r = idx & 31, d = idx >> 5;
            int gr = base + r;
            if (gr < NN) g_XT[(size_t)d * NP + gr] = xs[r][d];
        }
    } else if (b < DEC_B + TX_B + PWB_B) {
        // ---- prepWB layer 0 ----
        int i = (b - DEC_B - TX_B) * 256 + t;
        int k = i >> 7, n = i & 127;
        float v = (k < 512) ? sw[n * 512 + k] : bw[n * 128 + (k - 512)];
        unsigned short h, l;
        bfsplit(v, h, l);
        int c = k >> 5, kl = k & 31;
        int off = (c * 128 + n) * 32 + kl;
        g_WBh[off] = h;
        g_WBl[off] = l;
    } else {
        // ---- prepWO ----
        int i = (b - DEC_B - TX_B - PWB_B) * 256 + t;
        int k = i / 40, n = i % 40;
        float v = (k < 2048) ? swo[n * 2048 + k] : bwo[n * 512 + (k - 2048)];
        unsigned short h, l;
        bfsplit(v, h, l);
        int c = k >> 5, kl = k & 31;
        int off = c * 1280 + n * 32 + kl;
        g_WOh[off] = h;
        g_WOl[off] = l;
    }
}

// ------------------- multi-block scan: block sums (+dis) -> scan sums -> offsets ----------
__global__ void __launch_bounds__(256) k_scan1() {
    __shared__ int ws[8];
    int t = threadIdx.x;
    int i = blockIdx.x * 256 + t;
    int cv = (i < NN) ? g_cnt[i] : 0;
    if (i < NN) g_dis[i] = rsqrtf((float)(cv + 1));
    int s = cv;
    #pragma unroll
    for (int o = 16; o; o >>= 1) s += __shfl_xor_sync(0xffffffffu, s, o);
    if ((t & 31) == 0) ws[t >> 5] = s;
    __syncthreads();
    if (t < 8) {
        int v = ws[t];
        #pragma unroll
        for (int o = 4; o; o >>= 1) v += __shfl_xor_sync(0xffu, v, o);
        if (t == 0) g_bsum[blockIdx.x] = v;
    }
}
__global__ void __launch_bounds__(256) k_scan2(int nb) {
    __shared__ int ps[256];
    int t = threadIdx.x;
    int v = (t < nb) ? g_bsum[t] : 0;
    ps[t] = v;
    __syncthreads();
    #pragma unroll
    for (int d = 1; d < 256; d <<= 1) {
        int u = (t >= d) ? ps[t - d] : 0;
        __syncthreads();
        ps[t] += u;
        __syncthreads();
    }
    g_boff[t] = ps[t] - v;   // exclusive
    if (t == 255) g_off[NN] = ps[255];
}
__global__ void __launch_bounds__(256) k_scan3() {
    __shared__ int ps[256];
    int t = threadIdx.x;
    int i = blockIdx.x * 256 + t;
    int cv = (i < NN) ? g_cnt[i] : 0;
    ps[t] = cv;
    __syncthreads();
    #pragma unroll
    for (int d = 1; d < 256; d <<= 1) {
        int u = (t >= d) ? ps[t - d] : 0;
        __syncthreads();
        ps[t] += u;
        __syncthreads();
    }
    if (i < NN) g_off[i] = g_boff[blockIdx.x] + ps[t] - cv;
}
__global__ void k_fill() {
    int i = blockIdx.x * blockDim.x + threadIdx.x;
    if (i >= EE) return;
    int d = g_dst[i];
    int p = g_off[d] + atomicAdd(&g_fill[d], 1);
    g_csr[p] = g_src[i];
}

// ------------------- BN finalize(+apply) + transpose into XT + next-LN stats + out-LN partials
__global__ void __launch_bounds__(256) k_bnt(int rowBase, int statSet, int layer,
                                             const float* __restrict__ bng,
                                             const float* __restrict__ bnb) {
    __shared__ float xs[32][129];
    __shared__ float s_sc[128], s_of[128];
    int tid = threadIdx.x;
    int warp = tid >> 5, lane = tid & 31;
    int base = blockIdx.x * 32;
    if (tid < 128) {
        float S = 0.f, Q = 0.f;
        #pragma unroll
        for (int rp = 0; rp < NREP; rp++) { S += g_sumf[layer][rp][tid]; Q += g_sqf[layer][rp][tid]; }
        float m = S * (1.0f / NN);
        float var = Q * (1.0f / NN) - m * m;
        float sc = bng[tid] * rsqrtf(var + 1e-5f);
        s_sc[tid] = sc;
        s_of[tid] = bnb[tid] - m * sc;
    }
    __syncthreads();
    #pragma unroll
    for (int rr = 0; rr < 4; rr++) {
        int r = warp * 4 + rr;
        int gr = base + r;
        if (gr < NN) {
            float v[4];
            float s = 0.f, sq = 0.f;
            #pragma unroll
            for (int j = 0; j < 4; j++) {
                int c = lane + j * 32;
                v[j] = g_h2[(size_t)gr * HH + c] * s_sc[c] + s_of[c];
                s += v[j]; sq += v[j] * v[j];
            }
            #pragma unroll
            for (int o = 16; o; o >>= 1) {
                s  += __shfl_xor_sync(0xffffffffu, s, o);
                sq += __shfl_xor_sync(0xffffffffu, sq, o);
            }
            #pragma unroll
            for (int j = 0; j < 4; j++) xs[r][lane + j * 32] = v[j];
            if (lane == 0) {
                float mean = s * (1.0f / 128.0f);
                float var = sq * (1.0f / 128.0f) - mean * mean;
                g_mu[statSet][gr] = mean;
                g_rs[statSet][gr] = rsqrtf(var + 1e-5f);
                g_osum[gr] += s;
                g_osq[gr]  += sq;
            }
        }
    }
    __syncthreads();
    #pragma unroll 4
    for (int idx = tid; idx < 32 * 128; idx += 256) {
        int r = idx & 31, d = idx >> 5;
        int gr = base + r;
        if (gr < NN) g_XT[(size_t)(rowBase + d) * NP + gr] = xs[r][d];
    }
}

// ------------------- weight prep (layers 1,2) -------------------
__global__ void k_prepWB(const float* __restrict__ sw, const float* __restrict__ bw, int li) {
    int i = blockIdx.x * blockDim.x + threadIdx.x;
    if (i >= 640 * 128) return;
    int k = i >> 7, n = i & 127;
    sw += (size_t)li * 128 * 512;
    bw += (size_t)li * 128 * 128;
    float v = (k < 512) ? sw[n * 512 + k] : bw[n * 128 + (k - 512)];
    unsigned short h, l;
    bfsplit(v, h, l);
    int c = k >> 5, kl = k & 31;
    int off = (c * 128 + n) * 32 + kl;
    g_WBh[off] = h;
    g_WBl[off] = l;
}

// ------------------- A-chunk stores: LN+RBF or SiLU applied to prefetched raw values -----
__device__ __forceinline__ void store_basis(char* aAh, char* aAl, const float* pv,
                                            int r, int kh, float mu, float rs,
                                            const float* lg, const float* lb) {
    #pragma unroll
    for (int jp = 0; jp < 2; jp++) {
        uint32_t hv[4], lv[4];
        #pragma unroll
        for (int dd = 0; dd < 2; dd++) {
            int j = jp * 2 + dd;
            float xn = (pv[j] - mu) * rs * lg[j] + lb[j];
            float z0 = (xn + 2.0f) * 0.75f;
            float z1 = (xn + 0.66666667f) * 0.75f;
            float z2 = (xn - 0.66666667f) * 0.75f;
            float z3 = (xn - 2.0f) * 0.75f;
            float e0 = __expf(-z0 * z0), e1 = __expf(-z1 * z1);
            float e2 = __expf(-z2 * z2), e3 = __expf(-z3 * z3);
            hilo2(e0, e1, hv[dd * 2 + 0], lv[dd * 2 + 0]);
            hilo2(e2, e3, hv[dd * 2 + 1], lv[dd * 2 + 1]);
        }
        int kb = kh * 16 + jp * 8;
        *(uint4*)(aAh + (r * LSTR + kb) * 2) = make_uint4(hv[0], hv[1], hv[2], hv[3]);
        *(uint4*)(aAl + (r * LSTR + kb) * 2) = make_uint4(lv[0], lv[1], lv[2], lv[3]);
    }
}
__device__ __forceinline__ void store_silu(char* aAh, char* aAl, const float* pv, int r, int kh) {
    #pragma unroll
    for (int q = 0; q < 2; q++) {
        uint32_t hv[4], lv[4];
        #pragma unroll
        for (int p = 0; p < 4; p++) {
            float a = silu_f(pv[q * 8 + 2 * p]);
            float b = silu_f(pv[q * 8 + 2 * p + 1]);
            hilo2(a, b, hv[p], lv[p]);
        }
        int kb = kh * 16 + q * 8;
        *(uint4*)(aAh + (r * LSTR + kb) * 2) = make_uint4(hv[0], hv[1], hv[2], hv[3]);
        *(uint4*)(aAl + (r * LSTR + kb) * 2) = make_uint4(lv[0], lv[1], lv[2], lv[3]);
    }
}

// ------------------- layer GEMM (pipelined, 2 blocks/SM): h1 = dis*(A @ W^T + bb) ------
__global__ void __launch_bounds__(256, 2) k_mma_layer(const float* __restrict__ bb,
                                                      const float* __restrict__ lng,
                                                      const float* __restrict__ lnb,
                                                      int set) {
    extern __shared__ char sm[];
    __shared__ float s_lg[128], s_lb[128];
    const int BUF = 40960;   // Ah 10240 | Al 10240 | Bh 10240 | Bl 10240
    int tid = threadIdx.x, lane = tid & 31, w = tid >> 5;
    int bm = blockIdx.x * 128;
    int r = tid & 127, kh = tid >> 7;
    int m0 = (w & 3) * 32, n0 = (w >> 2) * 64;
    int rb = set * 128;

    if (tid < 128) { s_lg[tid] = lng[tid]; s_lb[tid] = lnb[tid]; }
    float mu = g_mu[set][bm + r];
    float rs = g_rs[set][bm + r];

    float acc[2][8][4];
    #pragma unroll
    for (int a = 0; a < 2; a++)
        #pragma unroll
        for (int b = 0; b < 8; b++)
            #pragma unroll
            for (int c = 0; c < 4; c++) acc[a][b][c] = 0.f;

    uint32_t sb = smem_u32(sm);
    uint32_t offA = ((m0 + (lane & 15)) * LSTR + (lane >> 4) * 8) * 2;
    uint32_t offB = ((n0 + (lane & 7) + ((lane & 16) ? 8 : 0)) * LSTR + ((lane >> 3) & 1) * 8) * 2;

    float pv[16];
    uint4 pbh[2], pbl[2];
    {
        int d0 = rb + kh * 4;
        #pragma unroll
        for (int j = 0; j < 4; j++) pv[j] = g_XT[(size_t)(d0 + j) * NP + bm + r];
        const uint4* sh = (const uint4*)g_WBh;
        const uint4* sl = (const uint4*)g_WBl;
        pbh[0] = sh[tid]; pbh[1] = sh[tid + 256];
        pbl[0] = sl[tid]; pbl[1] = sl[tid + 256];
    }
    __syncthreads();   // s_lg/s_lb ready

    for (int c = 0; c < 20; c++) {
        int cur = c & 1;
        char* base = sm + cur * BUF;
        if (c < 16) store_basis(base, base + 10240, pv, r, kh, mu, rs,
                                &s_lg[c * 8 + kh * 4], &s_lb[c * 8 + kh * 4]);
        else        store_silu (base, base + 10240, pv, r, kh);
        {
            int n = tid >> 2, kq = tid & 3;
            int i2 = tid + 256;
            int n2 = i2 >> 2, kq2 = i2 & 3;
            *(uint4*)(base + 20480 + (n * LSTR + kq * 8) * 2)  = pbh[0];
            *(uint4*)(base + 20480 + (n2 * LSTR + kq2 * 8) * 2) = pbh[1];
            *(uint4*)(base + 30720 + (n * LSTR + kq * 8) * 2)  = pbl[0];
            *(uint4*)(base + 30720 + (n2 * LSTR + kq2 * 8) * 2) = pbl[1];
        }
        __syncthreads();
        if (c < 19) {
            int cn = c + 1;
            if (cn < 16) {
                int d0 = rb + cn * 8 + kh * 4;
                #pragma unroll
                for (int j = 0; j < 4; j++) pv[j] = g_XT[(size_t)(d0 + j) * NP + bm + r];
            } else {
                int sd0 = rb + (cn - 16) * 32 + kh * 16;
                #pragma unroll
                for (int q = 0; q < 16; q++) pv[q] = g_XT[(size_t)(sd0 + q) * NP + bm + r];
            }
            const uint4* sh = (const uint4*)g_WBh + cn * 512;
            const uint4* sl = (const uint4*)g_WBl + cn * 512;
            pbh[0] = sh[tid]; pbh[1] = sh[tid + 256];
            pbl[0] = sl[tid]; pbl[1] = sl[tid + 256];
        }
        uint32_t aAh = sb + cur * BUF, aAl = aAh + 10240;
        uint32_t aBh = aAh + 20480,   aBl = aAh + 30720;
        #pragma unroll
        for (int ks = 0; ks < 2; ks++) {
            uint32_t kadd = ks * 32;
            uint32_t ah[2][4], al[2][4];
            ldsm4(ah[0][0], ah[0][1], ah[0][2], ah[0][3], aAh + offA + kadd);
            ldsm4(ah[1][0], ah[1][1], ah[1][2], ah[1][3], aAh + offA + kadd + 16 * LSTR * 2);
            ldsm4(al[0][0], al[0][1], al[0][2], al[0][3], aAl + offA + kadd);
            ldsm4(al[1][0], al[1][1], al[1][2], al[1][3], aAl + offA + kadd + 16 * LSTR * 2);
            #pragma unroll
            for (int p = 0; p < 4; p++) {
                uint32_t bh[4], bl[4];
                uint32_t po = (uint32_t)(p * 16 * LSTR * 2);
                ldsm4(bh[0], bh[1], bh[2], bh[3], aBh + offB + kadd + po);
                ldsm4(bl[0], bl[1], bl[2], bl[3], aBl + offB + kadd + po);
                #pragma unroll
                for (int mf = 0; mf < 2; mf++) {
                    mmabf(acc[mf][2 * p],     ah[mf], bh[0], bh[1]);
                    mmabf(acc[mf][2 * p],     ah[mf], bl[0], bl[1]);
                    mmabf(acc[mf][2 * p],     al[mf], bh[0], bh[1]);
                    mmabf(acc[mf][2 * p + 1], ah[mf], bh[2], bh[3]);
                    mmabf(acc[mf][2 * p + 1], ah[mf], bl[2], bl[3]);
                    mmabf(acc[mf][2 * p + 1], al[mf], bh[2], bh[3]);
                }
            }
        }
    }
    int gid = lane >> 2, tig = lane & 3;
    #pragma unroll
    for (int mf = 0; mf < 2; mf++) {
        int row = bm + m0 + mf * 16 + gid;
        float d0 = (row < NN) ? g_dis[row] : 0.f;
        float d1 = (row + 8 < NN) ? g_dis[row + 8] : 0.f;
        #pragma unroll
        for (int nf = 0; nf < 8; nf++) {
            int col = n0 + nf * 8 + tig * 2;
            if (row < NN) {
                float2 v = make_float2((acc[mf][nf][0] + bb[col]) * d0,
                                       (acc[mf][nf][1] + bb[col + 1]) * d0);
                *(float2*)&g_h1[(size_t)row * HH + col] = v;
            }
            if (row + 8 < NN) {
                float2 v = make_float2((acc[mf][nf][2] + bb[col]) * d1,
                                       (acc[mf][nf][3] + bb[col + 1]) * d1);
                *(float2*)&g_h1[(size_t)(row + 8) * HH + col] = v;
            }
        }
    }
}

// ------------------- output GEMM (pipelined, N=40, 2 blocks/SM) -------------------
__global__ void __launch_bounds__(256, 2) k_mma_out(const float* __restrict__ bbo,
                                                    const float* __restrict__ lng,
                                                    const float* __restrict__ lnb,
                                                    float* __restrict__ out) {
    extern __shared__ char sm[];
    __shared__ float s_lg[512], s_lb[512];
    const int BUF = 26880;   // Ah 10240 | Al 10240 | Bh 3200 | Bl 3200
    int tid = threadIdx.x, lane = tid & 31, w = tid >> 5;
    int bm = blockIdx.x * 128;
    int r = tid & 127, kh = tid >> 7;
    int m0 = w * 16;

    #pragma unroll
    for (int i = tid; i < 512; i += 256) { s_lg[i] = lng[i]; s_lb[i] = lnb[i]; }
    float mu, rs;
    {
        float s = g_osum[bm + r], sq = g_osq[bm + r];
        mu = s * (1.0f / 512.0f);
        float var = sq * (1.0f / 512.0f) - mu * mu;
        rs = rsqrtf(var + 1e-5f);
    }

    float acc[5][4];
    #pragma unroll
    for (int b = 0; b < 5; b++)
        #pragma unroll
        for (int c = 0; c < 4; c++) acc[b][c] = 0.f;

    uint32_t sb = smem_u32(sm);
    uint32_t offA  = ((m0 + (lane & 15)) * LSTR + (lane >> 4) * 8) * 2;
    uint32_t offB  = (((lane & 7) + ((lane & 16) ? 8 : 0)) * LSTR + ((lane >> 3) & 1) * 8) * 2;
    uint32_t offB2 = ((32 + (lane & 7)) * LSTR + ((lane >> 3) & 1) * 8) * 2;

    float pv[16];
    uint4 pbh, pbl;
    {
        int d0 = kh * 4;
        #pragma unroll
        for (int j = 0; j < 4; j++) pv[j] = g_XT[(size_t)(d0 + j) * NP + bm + r];
        if (tid < 160) {
            pbh = ((const uint4*)g_WOh)[tid];
            pbl = ((const uint4*)g_WOl)[tid];
        }
    }
    __syncthreads();   // s_lg/s_lb ready

    for (int c = 0; c < 80; c++) {
        int cur = c & 1;
        char* base = sm + cur * BUF;
        if (c < 64) store_basis(base, base + 10240, pv, r, kh, mu, rs,
                                &s_lg[c * 8 + kh * 4], &s_lb[c * 8 + kh * 4]);
        else        store_silu (base, base + 10240, pv, r, kh);
        if (tid < 160) {
            int n = tid >> 2, kq = tid & 3;
            *(uint4*)(base + 20480 + (n * LSTR + kq * 8) * 2) = pbh;
            *(uint4*)(base + 23680 + (n * LSTR + kq * 8) * 2) = pbl;
        }
        __syncthreads();
        if (c < 79) {
            int cn = c + 1;
            if (cn < 64) {
                int d0 = cn * 8 + kh * 4;
                #pragma unroll
                for (int j = 0; j < 4; j++) pv[j] = g_XT[(size_t)(d0 + j) * NP + bm + r];
            } else {
                int sd0 = (cn - 64) * 32 + kh * 16;
                #pragma unroll
                for (int q = 0; q < 16; q++) pv[q] = g_XT[(size_t)(sd0 + q) * NP + bm + r];
            }
            if (tid < 160) {
                pbh = ((const uint4*)g_WOh + cn * 160)[tid];
                pbl = ((const uint4*)g_WOl + cn * 160)[tid];
            }
        }
        uint32_t aAh = sb + cur * BUF, aAl = aAh + 10240;
        uint32_t aBh = aAh + 20480,   aBl = aAh + 23680;
        #pragma unroll
        for (int ks = 0; ks < 2; ks++) {
            uint32_t kadd = ks * 32;
            uint32_t ah[4], al[4];
            ldsm4(ah[0], ah[1], ah[2], ah[3], aAh + offA + kadd);
            ldsm4(al[0], al[1], al[2], al[3], aAl + offA + kadd);
            #pragma unroll
            for (int g = 0; g < 2; g++) {
                uint32_t bh[4], bl[4];
                uint32_t po = (uint32_t)(g * 16 * LSTR * 2);
                ldsm4(bh[0], bh[1], bh[2], bh[3], aBh + offB + kadd + po);
                ldsm4(bl[0], bl[1], bl[2], bl[3], aBl + offB + kadd + po);
                mmabf(acc[2 * g],     ah, bh[0], bh[1]);
                mmabf(acc[2 * g],     ah, bl[0], bl[1]);
                mmabf(acc[2 * g],     al, bh[0], bh[1]);
                mmabf(acc[2 * g + 1], ah, bh[2], bh[3]);
                mmabf(acc[2 * g + 1], ah, bl[2], bl[3]);
                mmabf(acc[2 * g + 1], al, bh[2], bh[3]);
            }
            {
                uint32_t b0, b1, c0, c1;
                ldsm2(b0, b1, aBh + offB2 + kadd);
                ldsm2(c0, c1, aBl + offB2 + kadd);
                mmabf(acc[4], ah, b0, b1);
                mmabf(acc[4], ah, c0, c1);
                mmabf(acc[4], al, b0, b1);
            }
        }
    }
    int gid = lane >> 2, tig = lane & 3;
    int row = bm + m0 + gid;
    #pragma unroll
    for (int nf = 0; nf < 5; nf++) {
        int col = nf * 8 + tig * 2;
        if (row < NN) {
            float2 v = make_float2(acc[nf][0] + bbo[col], acc[nf][1] + bbo[col + 1]);
            *(float2*)&out[(size_t)row * CC + col] = v;
        }
        if (row + 8 < NN) {
            float2 v = make_float2(acc[nf][2] + bbo[col], acc[nf][3] + bbo[col + 1]);
            *(float2*)&out[(size_t)(row + 8) * CC + col] = v;
        }
    }
}

// ------------------- GCN aggregation (1 node/warp, 4-deep pipelined) + BN stats -----------
__global__ void __launch_bounds__(256) k_gcn(int layer) {
    __shared__ float ssum[8][128];
    __shared__ float ssq[8][128];
    int tid = threadIdx.x, w = tid >> 5, l = tid & 31;
    int node = blockIdx.x * 8 + w;
    float4 rr = make_float4(0.f, 0.f, 0.f, 0.f);
    if (node < NN) {
        float dn = g_dis[node];
        float4 acc = *(const float4*)(g_h1 + (size_t)node * HH + l * 4);
        int lo = g_off[node], hi = g_off[node + 1];
        int e = lo;
        // 4-deep software pipeline: batch index loads, then 4 independent gathers
        for (; e + 4 <= hi; e += 4) {
            int s0 = g_csr[e + 0];
            int s1 = g_csr[e + 1];
            int s2 = g_csr[e + 2];
            int s3 = g_csr[e + 3];
            float4 h0 = *(const float4*)(g_h1 + (size_t)s0 * HH + l * 4);
            float4 h1v = *(const float4*)(g_h1 + (size_t)s1 * HH + l * 4);
            float4 h2v = *(const float4*)(g_h1 + (size_t)s2 * HH + l * 4);
            float4 h3 = *(const float4*)(g_h1 + (size_t)s3 * HH + l * 4);
            acc.x += (h0.x + h1v.x) + (h2v.x + h3.x);
            acc.y += (h0.y + h1v.y) + (h2v.y + h3.y);
            acc.z += (h0.z + h1v.z) + (h2v.z + h3.z);
            acc.w += (h0.w + h1v.w) + (h2v.w + h3.w);
        }
        for (; e < hi; e++) {
            int sidx = g_csr[e];
            float4 hv = *(const float4*)(g_h1 + (size_t)sidx * HH + l * 4);
            acc.x += hv.x; acc.y += hv.y; acc.z += hv.z; acc.w += hv.w;
        }
        rr = make_float4(dn * acc.x, dn * acc.y, dn * acc.z, dn * acc.w);
        *(float4*)(g_h2 + (size_t)node * HH + l * 4) = rr;
    }
    ssum[w][l * 4 + 0] = rr.x; ssum[w][l * 4 + 1] = rr.y;
    ssum[w][l * 4 + 2] = rr.z; ssum[w][l * 4 + 3] = rr.w;
    ssq[w][l * 4 + 0] = rr.x * rr.x; ssq[w][l * 4 + 1] = rr.y * rr.y;
    ssq[w][l * 4 + 2] = rr.z * rr.z; ssq[w][l * 4 + 3] = rr.w * rr.w;
    __syncthreads();
    if (tid < 128) {
        float S = 0.f, Q = 0.f;
        #pragma unroll
        for (int w2 = 0; w2 < 8; w2++) { S += ssum[w2][tid]; Q += ssq[w2][tid]; }
        int rp = blockIdx.x & (NREP - 1);
        atomicAdd(&g_sumf[layer][rp][tid], S);
        atomicAdd(&g_sqf[layer][rp][tid], Q);
    }
}

// ------------------- launch (single stream — graph-capture-safe, no statics) -------------------
extern "C" void kernel_launch(void* const* d_in, const int* in_sizes, int n_in,
                              void* d_out, int out_size) {
    const float* x      = (const float*)d_in[0];
    const void*  eidx   = d_in[1];
    const float* ln_g   = (const float*)d_in[2];
    const float* ln_b   = (const float*)d_in[3];
    const float* sw     = (const float*)d_in[4];
    const float* bw     = (const float*)d_in[5];
    const float* bb     = (const float*)d_in[6];
    // d_in[7] = gcn_bias: cancelled exactly by the following BatchNorm -> skipped
    const float* bn_g   = (const float*)d_in[8];
    const float* bn_b   = (const float*)d_in[9];
    const float* ln_go  = (const float*)d_in[10];
    const float* ln_bo  = (const float*)d_in[11];
    const float* sw_o   = (const float*)d_in[12];
    const float* bw_o   = (const float*)d_in[13];
    const float* bb_o   = (const float*)d_in[14];
    float* out = (float*)d_out;

    const int SMEM_L = 2 * 40960;   // 81920
    const int SMEM_O = 2 * 26880;   // 53760
    cudaFuncSetAttribute(k_mma_layer, cudaFuncAttributeMaxDynamicSharedMemorySize, SMEM_L);
    cudaFuncSetAttribute(k_mma_out,   cudaFuncAttributeMaxDynamicSharedMemorySize, SMEM_O);

    const int NB = (NN + 255) / 256;  // 196 scan blocks
    const int GT = (NN + 127) / 128;  // 391 M-tiles

    // init: zero counters/stats, then fused decode|tx|prepWB0|prepWO
    k_zero_cnt<<<(NN + 255) / 256, 256>>>();
    k_mega<<<DEC_B + TX_B + PWB_B + PWO_B, 256>>>(eidx, x, sw, bw, sw_o, bw_o);

    // CSR offsets + fill
    k_scan1<<<NB, 256>>>();
    k_scan2<<<1, 256>>>(NB);
    k_scan3<<<NB, 256>>>();
    k_fill<<<(EE + 255) / 256, 256>>>();

    for (int i = 0; i < LL; i++) {
        if (i > 0) k_prepWB<<<(640 * 128 + 255) / 256, 256>>>(sw, bw, i);
        k_mma_layer<<<GT, 256, SMEM_L>>>(bb + i * HH, ln_g + i * DD, ln_b + i * DD, i);
        k_gcn<<<(NN + 7) / 8, 256>>>(i);
        k_bnt<<<(NN + 31) / 32, 256>>>((i + 1) * 128, i + 1, i, bn_g + i * HH, bn_b + i * HH);
    }

    k_mma_out<<<GT, 256, SMEM_O>>>(bb_o, ln_go, ln_bo, out);
}

// round 15
// speedup vs baseline: 1.0037x; 1.0037x over previous
#include <cuda_runtime.h>
#include <cstdint>

#define NN 50000
#define NP 50048      // padded node stride for transposed tensors
#define DD 128
#define HH 128
#define CC 40
#define LL 3
#define EE 800000
#define LSTR 40       // padded SMEM row stride in bf16 units (80 bytes)
#define NREP 16       // BN stat replica buffers

// mega-kernel block ranges
#define DEC_B 3125            // decode blocks (EE/256)
#define TX_B  1563            // tx blocks (NN/32)
#define PWB_B 320             // prepWB(0) blocks (640*128/256)
#define PWO_B 400             // prepWO blocks (2560*40/256)

// ------------------- device scratch (static: no allocation) -------------------
__device__ int    g_src[EE];
__device__ int    g_dst[EE];
__device__ float  g_dis[NN];
__device__ int    g_cnt[NN];
__device__ int    g_off[NN + 1];
__device__ int    g_fill[NN];
__device__ int    g_csr[EE];
__device__ unsigned long long g_desc[256];   // decoupled-lookback descriptors
__device__ float  g_XT[(size_t)512 * NP];    // transposed raw values [d][n]
__device__ float  g_mu[4][NP];               // per-LN-set node mean
__device__ float  g_rs[4][NP];               // per-LN-set node rstd
__device__ float  g_osum[NP];                // output-LN partial: sum over 512 dims
__device__ float  g_osq[NP];                 // output-LN partial: sumsq
__device__ float  g_h1[(size_t)NN * HH];     // pre-scaled by dis[row]
__device__ float  g_h2[(size_t)NN * HH];
__device__ unsigned short g_WBh[20 * 128 * 32];   // layer B bf16-hi [chunk][n][k]
__device__ unsigned short g_WBl[20 * 128 * 32];
__device__ unsigned short g_WOh[80 * 40 * 32];    // output B bf16-hi [chunk][n][k]
__device__ unsigned short g_WOl[80 * 40 * 32];
__device__ float  g_sumf[LL][NREP][HH];      // per-layer BN column sums (replicated)
__device__ float  g_sqf[LL][NREP][HH];       // per-layer BN column sumsq

// ------------------- helpers -------------------
__device__ __forceinline__ uint32_t smem_u32(const void* p) {
    uint32_t a;
    asm("{ .reg .u64 t; cvta.to.shared.u64 t, %1; cvt.u32.u64 %0, t; }" : "=r"(a) : "l"(p));
    return a;
}
__device__ __forceinline__ uint32_t pkbf(float a, float b) {   // [bf16(a) lo16 | bf16(b) hi16]
    uint32_t r;
    asm("cvt.rn.bf16x2.f32 %0, %1, %2;" : "=r"(r) : "f"(b), "f"(a));
    return r;
}
__device__ __forceinline__ float lo2f(uint32_t v) { return __uint_as_float(v << 16); }
__device__ __forceinline__ float hi2f(uint32_t v) { return __uint_as_float(v & 0xffff0000u); }

__device__ __forceinline__ void ldsm4(uint32_t& r0, uint32_t& r1, uint32_t& r2, uint32_t& r3,
                                      uint32_t a) {
    asm volatile("ldmatrix.sync.aligned.m8n8.x4.shared.b16 {%0,%1,%2,%3}, [%4];"
                 : "=r"(r0), "=r"(r1), "=r"(r2), "=r"(r3) : "r"(a));
}
__device__ __forceinline__ void ldsm2(uint32_t& r0, uint32_t& r1, uint32_t a) {
    asm volatile("ldmatrix.sync.aligned.m8n8.x2.shared.b16 {%0,%1}, [%2];"
                 : "=r"(r0), "=r"(r1) : "r"(a));
}
__device__ __forceinline__ void mmabf(float* c, const uint32_t* a, uint32_t b0, uint32_t b1) {
    asm volatile("mma.sync.aligned.m16n8k16.row.col.f32.bf16.bf16.f32 "
                 "{%0,%1,%2,%3}, {%4,%5,%6,%7}, {%8,%9}, {%0,%1,%2,%3};"
                 : "+f"(c[0]), "+f"(c[1]), "+f"(c[2]), "+f"(c[3])
                 : "r"(a[0]), "r"(a[1]), "r"(a[2]), "r"(a[3]), "r"(b0), "r"(b1));
}
__device__ __forceinline__ void hilo2(float v0, float v1, uint32_t& h, uint32_t& l) {
    h = pkbf(v0, v1);
    l = pkbf(v0 - lo2f(h), v1 - hi2f(h));
}
__device__ __forceinline__ float silu_f(float v) {
    return __fdividef(v, 1.0f + __expf(-v));
}
__device__ __forceinline__ void bfsplit(float v, unsigned short& h, unsigned short& l) {
    asm("cvt.rn.bf16.f32 %0, %1;" : "=h"(h) : "f"(v));
    float vl = v - __uint_as_float(((uint32_t)h) << 16);
    asm("cvt.rn.bf16.f32 %0, %1;" : "=h"(l) : "f"(vl));
}

// ------------------- zero counters + per-layer BN stats + scan descriptors ----------------
__global__ void k_zero_cnt() {
    int i = blockIdx.x * blockDim.x + threadIdx.x;
    if (i < NN) { g_cnt[i] = 0; g_fill[i] = 0; }
    if (i < LL * NREP * HH) {
        ((float*)g_sumf)[i] = 0.f;
        ((float*)g_sqf)[i]  = 0.f;
    }
    if (i < 256) g_desc[i] = 0ull;
}

// ------------------- MEGA init kernel: decode | tx | prepWB(0) | prepWO -------------------
__global__ void __launch_bounds__(256) k_mega(const void* ep, const float* __restrict__ x,
                                              const float* __restrict__ sw,
                                              const float* __restrict__ bw,
                                              const float* __restrict__ swo,
                                              const float* __restrict__ bwo) {
    int b = blockIdx.x, t = threadIdx.x;
    if (b < DEC_B) {
        // ---- edge decode + degree histogram (dtype self-detected per block) ----
        __shared__ int sflag;
        if (t == 0) {
            const unsigned* e = (const unsigned*)ep;
            int z = 0;
            #pragma unroll
            for (int i = 0; i < 16; i++) z += (e[2 * i + 1] == 0u) ? 1 : 0;
            sflag = (z == 16) ? 1 : 0;
        }
        __syncthreads();
        int i = b * 256 + t;
        if (i < EE) {
            int s, d;
            if (sflag) {
                const long long* e = (const long long*)ep;
                s = (int)e[i];
                d = (int)e[EE + i];
            } else {
                const int* e = (const int*)ep;
                s = e[i];
                d = e[EE + i];
            }
            g_src[i] = s;
            g_dst[i] = d;
            atomicAdd(&g_cnt[d], 1);
        }
    } else if (b < DEC_B + TX_B) {
        // ---- x transpose + LN0 stats + output-LN partial init ----
        __shared__ float xs[32][129];
        int warp = t >> 5, lane = t & 31;
        int base = (b - DEC_B) * 32;
        #pragma unroll
        for (int rr = 0; rr < 4; rr++) {
            int r = warp * 4 + rr;
            int gr = base + r;
            if (gr < NN) {
                float v[4];
                float s = 0.f, sq = 0.f;
                #pragma unroll
                for (int j = 0; j < 4; j++) {
                    v[j] = x[(size_t)gr * DD + lane + j * 32];
                    s += v[j]; sq += v[j] * v[j];
                }
                #pragma unroll
                for (int o = 16; o; o >>= 1) {
                    s  += __shfl_xor_sync(0xffffffffu, s, o);
                    sq += __shfl_xor_sync(0xffffffffu, sq, o);
                }
                #pragma unroll
                for (int j = 0; j < 4; j++) xs[r][lane + j * 32] = v[j];
                if (lane == 0) {
                    float mean = s * (1.0f / 128.0f);
                    float var = sq * (1.0f / 128.0f) - mean * mean;
                    g_mu[0][gr] = mean;
                    g_rs[0][gr] = rsqrtf(var + 1e-5f);
                    g_osum[gr] = s;
                    g_osq[gr]  = sq;
                }
            }
        }
        __syncthreads();
        #pragma unroll 4
        for (int idx = t; idx < 32 * 128; idx += 256) {
            int r = idx & 31, d = idx >> 5;
            int gr = base + r;
            if (gr < NN) g_XT[(size_t)d * NP + gr] = xs[r][d];
        }
    } else if (b < DEC_B + TX_B + PWB_B) {
        // ---- prepWB layer 0 ----
        int i = (b - DEC_B - TX_B) * 256 + t;
        int k = i >> 7, n = i & 127;
        float v = (k < 512) ? sw[n * 512 + k] : bw[n * 128 + (k - 512)];
        unsigned short h, l;
        bfsplit(v, h, l);
        int c = k >> 5, kl = k & 31;
        int off = (c * 128 + n) * 32 + kl;
        g_WBh[off] = h;
        g_WBl[off] = l;
    } else {
        // ---- prepWO ----
        int i = (b - DEC_B - TX_B - PWB_B) * 256 + t;
        int k = i / 40, n = i % 40;
        float v = (k < 2048) ? swo[n * 2048 + k] : bwo[n * 512 + (k - 2048)];
        unsigned short h, l;
        bfsplit(v, h, l);
        int c = k >> 5, kl = k & 31;
        int off = c * 1280 + n * 32 + kl;
        g_WOh[off] = h;
        g_WOl[off] = l;
    }
}

// ------------------- single-pass decoupled-lookback scan (+dis) -------------------
// desc[b] = (flag<<32)|value; flag 1 = block sum, flag 2 = inclusive prefix.
// Single 8B volatile store keeps flag+value atomic; blocks only wait on lower IDs.
__global__ void __launch_bounds__(256) k_scanf() {
    __shared__ int ps[256];
    __shared__ int s_excl;
    int b = blockIdx.x, t = threadIdx.x, lane = t & 31;
    int i = b * 256 + t;
    int cv = (i < NN) ? g_cnt[i] : 0;
    if (i < NN) g_dis[i] = rsqrtf((float)(cv + 1));
    ps[t] = cv;
    __syncthreads();
    #pragma unroll
    for (int d = 1; d < 256; d <<= 1) {
        int u = (t >= d) ? ps[t - d] : 0;
        __syncthreads();
        ps[t] += u;
        __syncthreads();
    }
    int bsum = ps[255];
    if (t == 0)
        *((volatile unsigned long long*)&g_desc[b]) = (1ull << 32) | (unsigned)bsum;
    if (t < 32) {
        int run = 0;
        int idx = b - 1;
        while (idx >= 0) {
            int j = idx - lane;
            int f = 0, v = 0;
            if (j >= 0) {
                unsigned long long d;
                do {
                    d = *((volatile unsigned long long*)&g_desc[j]);
                    f = (int)(d >> 32);
                } while (f == 0);
                v = (int)(unsigned)d;
            }
            unsigned m = __ballot_sync(0xffffffffu, (j >= 0) && (f == 2));
            int cut = m ? (__ffs(m) - 1) : 32;
            int contrib = ((j >= 0) && (lane <= cut)) ? v : 0;
            #pragma unroll
            for (int o = 16; o; o >>= 1) contrib += __shfl_xor_sync(0xffffffffu, contrib, o);
            run += contrib;
            if (m) break;
            idx -= 32;
        }
        if (lane == 0) {
            *((volatile unsigned long long*)&g_desc[b]) = (2ull << 32) | (unsigned)(run + bsum);
            s_excl = run;
        }
    }
    __syncthreads();
    int excl = s_excl;
    if (i < NN) g_off[i] = excl + ps[t] - cv;
    if (i == NN - 1) g_off[NN] = excl + ps[t];
}

__global__ void k_fill() {
    int i = blockIdx.x * blockDim.x + threadIdx.x;
    if (i >= EE) return;
    int d = g_dst[i];
    int p = g_off[d] + atomicAdd(&g_fill[d], 1);
    g_csr[p] = g_src[i];
}

// ------------------- BN finalize(+apply) + transpose into XT + next-LN stats + out-LN partials
__global__ void __launch_bounds__(256) k_bnt(int rowBase, int statSet, int layer,
                                             const float* __restrict__ bng,
                                             const float* __restrict__ bnb) {
    __shared__ float xs[32][129];
    __shared__ float s_sc[128], s_of[128];
    int tid = threadIdx.x;
    int warp = tid >> 5, lane = tid & 31;
    int base = blockIdx.x * 32;
    if (tid < 128) {
        float S = 0.f, Q = 0.f;
        #pragma unroll
        for (int rp = 0; rp < NREP; rp++) { S += g_sumf[layer][rp][tid]; Q += g_sqf[layer][rp][tid]; }
        float m = S * (1.0f / NN);
        float var = Q * (1.0f / NN) - m * m;
        float sc = bng[tid] * rsqrtf(var + 1e-5f);
        s_sc[tid] = sc;
        s_of[tid] = bnb[tid] - m * sc;
    }
    __syncthreads();
    #pragma unroll
    for (int rr = 0; rr < 4; rr++) {
        int r = warp * 4 + rr;
        int gr = base + r;
        if (gr < NN) {
            float v[4];
            float s = 0.f, sq = 0.f;
            #pragma unroll
            for (int j = 0; j < 4; j++) {
                int c = lane + j * 32;
                v[j] = g_h2[(size_t)gr * HH + c] * s_sc[c] + s_of[c];
                s += v[j]; sq += v[j] * v[j];
            }
            #pragma unroll
            for (int o = 16; o; o >>= 1) {
                s  += __shfl_xor_sync(0xffffffffu, s, o);
                sq += __shfl_xor_sync(0xffffffffu, sq, o);
            }
            #pragma unroll
            for (int j = 0; j < 4; j++) xs[r][lane + j * 32] = v[j];
            if (lane == 0) {
                float mean = s * (1.0f / 128.0f);
                float var = sq * (1.0f / 128.0f) - mean * mean;
                g_mu[statSet][gr] = mean;
                g_rs[statSet][gr] = rsqrtf(var + 1e-5f);
                g_osum[gr] += s;
                g_osq[gr]  += sq;
            }
        }
    }
    __syncthreads();
    #pragma unroll 4
    for (int idx = tid; idx < 32 * 128; idx += 256) {
        int r = idx & 31, d = idx >> 5;
        int gr = base + r;
        if (gr < NN) g_XT[(size_t)(rowBase + d) * NP + gr] = xs[r][d];
    }
}

// ------------------- weight prep (layers 1,2) -------------------
__global__ void k_prepWB(const float* __restrict__ sw, const float* __restrict__ bw, int li) {
    int i = blockIdx.x * blockDim.x + threadIdx.x;
    if (i >= 640 * 128) return;
    int k = i >> 7, n = i & 127;
    sw += (size_t)li * 128 * 512;
    bw += (size_t)li * 128 * 128;
    float v = (k < 512) ? sw[n * 512 + k] : bw[n * 128 + (k - 512)];
    unsigned short h, l;
    bfsplit(v, h, l);
    int c = k >> 5, kl = k & 31;
    int off = (c * 128 + n) * 32 + kl;
    g_WBh[off] = h;
    g_WBl[off] = l;
}

// ------------------- A-chunk stores: LN+RBF or SiLU applied to prefetched raw values -----
__device__ __forceinline__ void store_basis(char* aAh, char* aAl, const float* pv,
                                            int r, int kh, float mu, float rs,
                                            const float* lg, const float* lb) {
    #pragma unroll
    for (int jp = 0; jp < 2; jp++) {
        uint32_t hv[4], lv[4];
        #pragma unroll
        for (int dd = 0; dd < 2; dd++) {
            int j = jp * 2 + dd;
            float xn = (pv[j] - mu) * rs * lg[j] + lb[j];
            float z0 = (xn + 2.0f) * 0.75f;
            float z1 = (xn + 0.66666667f) * 0.75f;
            float z2 = (xn - 0.66666667f) * 0.75f;
            float z3 = (xn - 2.0f) * 0.75f;
            float e0 = __expf(-z0 * z0), e1 = __expf(-z1 * z1);
            float e2 = __expf(-z2 * z2), e3 = __expf(-z3 * z3);
            hilo2(e0, e1, hv[dd * 2 + 0], lv[dd * 2 + 0]);
            hilo2(e2, e3, hv[dd * 2 + 1], lv[dd * 2 + 1]);
        }
        int kb = kh * 16 + jp * 8;
        *(uint4*)(aAh + (r * LSTR + kb) * 2) = make_uint4(hv[0], hv[1], hv[2], hv[3]);
        *(uint4*)(aAl + (r * LSTR + kb) * 2) = make_uint4(lv[0], lv[1], lv[2], lv[3]);
    }
}
__device__ __forceinline__ void store_silu(char* aAh, char* aAl, const float* pv, int r, int kh) {
    #pragma unroll
    for (int q = 0; q < 2; q++) {
        uint32_t hv[4], lv[4];
        #pragma unroll
        for (int p = 0; p < 4; p++) {
            float a = silu_f(pv[q * 8 + 2 * p]);
            float b = silu_f(pv[q * 8 + 2 * p + 1]);
            hilo2(a, b, hv[p], lv[p]);
        }
        int kb = kh * 16 + q * 8;
        *(uint4*)(aAh + (r * LSTR + kb) * 2) = make_uint4(hv[0], hv[1], hv[2], hv[3]);
        *(uint4*)(aAl + (r * LSTR + kb) * 2) = make_uint4(lv[0], lv[1], lv[2], lv[3]);
    }
}

// ------------------- layer GEMM (pipelined, 2 blocks/SM): h1 = dis*(A @ W^T + bb) ------
__global__ void __launch_bounds__(256, 2) k_mma_layer(const float* __restrict__ bb,
                                                      const float* __restrict__ lng,
                                                      const float* __restrict__ lnb,
                                                      int set) {
    extern __shared__ char sm[];
    __shared__ float s_lg[128], s_lb[128];
    const int BUF = 40960;   // Ah 10240 | Al 10240 | Bh 10240 | Bl 10240
    int tid = threadIdx.x, lane = tid & 31, w = tid >> 5;
    int bm = blockIdx.x * 128;
    int r = tid & 127, kh = tid >> 7;
    int m0 = (w & 3) * 32, n0 = (w >> 2) * 64;
    int rb = set * 128;

    if (tid < 128) { s_lg[tid] = lng[tid]; s_lb[tid] = lnb[tid]; }
    float mu = g_mu[set][bm + r];
    float rs = g_rs[set][bm + r];

    float acc[2][8][4];
    #pragma unroll
    for (int a = 0; a < 2; a++)
        #pragma unroll
        for (int b = 0; b < 8; b++)
            #pragma unroll
            for (int c = 0; c < 4; c++) acc[a][b][c] = 0.f;

    uint32_t sb = smem_u32(sm);
    uint32_t offA = ((m0 + (lane & 15)) * LSTR + (lane >> 4) * 8) * 2;
    uint32_t offB = ((n0 + (lane & 7) + ((lane & 16) ? 8 : 0)) * LSTR + ((lane >> 3) & 1) * 8) * 2;

    float pv[16];
    uint4 pbh[2], pbl[2];
    {
        int d0 = rb + kh * 4;
        #pragma unroll
        for (int j = 0; j < 4; j++) pv[j] = g_XT[(size_t)(d0 + j) * NP + bm + r];
        const uint4* sh = (const uint4*)g_WBh;
        const uint4* sl = (const uint4*)g_WBl;
        pbh[0] = sh[tid]; pbh[1] = sh[tid + 256];
        pbl[0] = sl[tid]; pbl[1] = sl[tid + 256];
    }
    __syncthreads();   // s_lg/s_lb ready

    for (int c = 0; c < 20; c++) {
        int cur = c & 1;
        char* base = sm + cur * BUF;
        if (c < 16) store_basis(base, base + 10240, pv, r, kh, mu, rs,
                                &s_lg[c * 8 + kh * 4], &s_lb[c * 8 + kh * 4]);
        else        store_silu (base, base + 10240, pv, r, kh);
        {
            int n = tid >> 2, kq = tid & 3;
            int i2 = tid + 256;
            int n2 = i2 >> 2, kq2 = i2 & 3;
            *(uint4*)(base + 20480 + (n * LSTR + kq * 8) * 2)  = pbh[0];
            *(uint4*)(base + 20480 + (n2 * LSTR + kq2 * 8) * 2) = pbh[1];
            *(uint4*)(base + 30720 + (n * LSTR + kq * 8) * 2)  = pbl[0];
            *(uint4*)(base + 30720 + (n2 * LSTR + kq2 * 8) * 2) = pbl[1];
        }
        __syncthreads();
        if (c < 19) {
            int cn = c + 1;
            if (cn < 16) {
                int d0 = rb + cn * 8 + kh * 4;
                #pragma unroll
                for (int j = 0; j < 4; j++) pv[j] = g_XT[(size_t)(d0 + j) * NP + bm + r];
            } else {
                int sd0 = rb + (cn - 16) * 32 + kh * 16;
                #pragma unroll
                for (int q = 0; q < 16; q++) pv[q] = g_XT[(size_t)(sd0 + q) * NP + bm + r];
            }
            const uint4* sh = (const uint4*)g_WBh + cn * 512;
            const uint4* sl = (const uint4*)g_WBl + cn * 512;
            pbh[0] = sh[tid]; pbh[1] = sh[tid + 256];
            pbl[0] = sl[tid]; pbl[1] = sl[tid + 256];
        }
        uint32_t aAh = sb + cur * BUF, aAl = aAh + 10240;
        uint32_t aBh = aAh + 20480,   aBl = aAh + 30720;
        #pragma unroll
        for (int ks = 0; ks < 2; ks++) {
            uint32_t kadd = ks * 32;
            uint32_t ah[2][4], al[2][4];
            ldsm4(ah[0][0], ah[0][1], ah[0][2], ah[0][3], aAh + offA + kadd);
            ldsm4(ah[1][0], ah[1][1], ah[1][2], ah[1][3], aAh + offA + kadd + 16 * LSTR * 2);
            ldsm4(al[0][0], al[0][1], al[0][2], al[0][3], aAl + offA + kadd);
            ldsm4(al[1][0], al[1][1], al[1][2], al[1][3], aAl + offA + kadd + 16 * LSTR * 2);
            #pragma unroll
            for (int p = 0; p < 4; p++) {
                uint32_t bh[4], bl[4];
                uint32_t po = (uint32_t)(p * 16 * LSTR * 2);
                ldsm4(bh[0], bh[1], bh[2], bh[3], aBh + offB + kadd + po);
                ldsm4(bl[0], bl[1], bl[2], bl[3], aBl + offB + kadd + po);
                #pragma unroll
                for (int mf = 0; mf < 2; mf++) {
                    mmabf(acc[mf][2 * p],     ah[mf], bh[0], bh[1]);
                    mmabf(acc[mf][2 * p],     ah[mf], bl[0], bl[1]);
                    mmabf(acc[mf][2 * p],     al[mf], bh[0], bh[1]);
                    mmabf(acc[mf][2 * p + 1], ah[mf], bh[2], bh[3]);
                    mmabf(acc[mf][2 * p + 1], ah[mf], bl[2], bl[3]);
                    mmabf(acc[mf][2 * p + 1], al[mf], bh[2], bh[3]);
                }
            }
        }
    }
    int gid = lane >> 2, tig = lane & 3;
    #pragma unroll
    for (int mf = 0; mf < 2; mf++) {
        int row = bm + m0 + mf * 16 + gid;
        float d0 = (row < NN) ? g_dis[row] : 0.f;
        float d1 = (row + 8 < NN) ? g_dis[row + 8] : 0.f;
        #pragma unroll
        for (int nf = 0; nf < 8; nf++) {
            int col = n0 + nf * 8 + tig * 2;
            if (row < NN) {
                float2 v = make_float2((acc[mf][nf][0] + bb[col]) * d0,
                                       (acc[mf][nf][1] + bb[col + 1]) * d0);
                *(float2*)&g_h1[(size_t)row * HH + col] = v;
            }
            if (row + 8 < NN) {
                float2 v = make_float2((acc[mf][nf][2] + bb[col]) * d1,
                                       (acc[mf][nf][3] + bb[col + 1]) * d1);
                *(float2*)&g_h1[(size_t)(row + 8) * HH + col] = v;
            }
        }
    }
}

// ------------------- output GEMM (pipelined, N=40, 2 blocks/SM) -------------------
__global__ void __launch_bounds__(256, 2) k_mma_out(const float* __restrict__ bbo,
                                                    const float* __restrict__ lng,
                                                    const float* __restrict__ lnb,
                                                    float* __restrict__ out) {
    extern __shared__ char sm[];
    __shared__ float s_lg[512], s_lb[512];
    const int BUF = 26880;   // Ah 10240 | Al 10240 | Bh 3200 | Bl 3200
    int tid = threadIdx.x, lane = tid & 31, w = tid >> 5;
    int bm = blockIdx.x * 128;
    int r = tid & 127, kh = tid >> 7;
    int m0 = w * 16;

    #pragma unroll
    for (int i = tid; i < 512; i += 256) { s_lg[i] = lng[i]; s_lb[i] = lnb[i]; }
    float mu, rs;
    {
        float s = g_osum[bm + r], sq = g_osq[bm + r];
        mu = s * (1.0f / 512.0f);
        float var = sq * (1.0f / 512.0f) - mu * mu;
        rs = rsqrtf(var + 1e-5f);
    }

    float acc[5][4];
    #pragma unroll
    for (int b = 0; b < 5; b++)
        #pragma unroll
        for (int c = 0; c < 4; c++) acc[b][c] = 0.f;

    uint32_t sb = smem_u32(sm);
    uint32_t offA  = ((m0 + (lane & 15)) * LSTR + (lane >> 4) * 8) * 2;
    uint32_t offB  = (((lane & 7) + ((lane & 16) ? 8 : 0)) * LSTR + ((lane >> 3) & 1) * 8) * 2;
    uint32_t offB2 = ((32 + (lane & 7)) * LSTR + ((lane >> 3) & 1) * 8) * 2;

    float pv[16];
    uint4 pbh, pbl;
    {
        int d0 = kh * 4;
        #pragma unroll
        for (int j = 0; j < 4; j++) pv[j] = g_XT[(size_t)(d0 + j) * NP + bm + r];
        if (tid < 160) {
            pbh = ((const uint4*)g_WOh)[tid];
            pbl = ((const uint4*)g_WOl)[tid];
        }
    }
    __syncthreads();   // s_lg/s_lb ready

    for (int c = 0; c < 80; c++) {
        int cur = c & 1;
        char* base = sm + cur * BUF;
        if (c < 64) store_basis(base, base + 10240, pv, r, kh, mu, rs,
                                &s_lg[c * 8 + kh * 4], &s_lb[c * 8 + kh * 4]);
        else        store_silu (base, base + 10240, pv, r, kh);
        if (tid < 160) {
            int n = tid >> 2, kq = tid & 3;
            *(uint4*)(base + 20480 + (n * LSTR + kq * 8) * 2) = pbh;
            *(uint4*)(base + 23680 + (n * LSTR + kq * 8) * 2) = pbl;
        }
        __syncthreads();
        if (c < 79) {
            int cn = c + 1;
            if (cn < 64) {
                int d0 = cn * 8 + kh * 4;
                #pragma unroll
                for (int j = 0; j < 4; j++) pv[j] = g_XT[(size_t)(d0 + j) * NP + bm + r];
            } else {
                int sd0 = (cn - 64) * 32 + kh * 16;
                #pragma unroll
                for (int q = 0; q < 16; q++) pv[q] = g_XT[(size_t)(sd0 + q) * NP + bm + r];
            }
            if (tid < 160) {
                pbh = ((const uint4*)g_WOh + cn * 160)[tid];
                pbl = ((const uint4*)g_WOl + cn * 160)[tid];
            }
        }
        uint32_t aAh = sb + cur * BUF, aAl = aAh + 10240;
        uint32_t aBh = aAh + 20480,   aBl = aAh + 23680;
        #pragma unroll
        for (int ks = 0; ks < 2; ks++) {
            uint32_t kadd = ks * 32;
            uint32_t ah[4], al[4];
            ldsm4(ah[0], ah[1], ah[2], ah[3], aAh + offA + kadd);
            ldsm4(al[0], al[1], al[2], al[3], aAl + offA + kadd);
            #pragma unroll
            for (int g = 0; g < 2; g++) {
                uint32_t bh[4], bl[4];
                uint32_t po = (uint32_t)(g * 16 * LSTR * 2);
                ldsm4(bh[0], bh[1], bh[2], bh[3], aBh + offB + kadd + po);
                ldsm4(bl[0], bl[1], bl[2], bl[3], aBl + offB + kadd + po);
                mmabf(acc[2 * g],     ah, bh[0], bh[1]);
                mmabf(acc[2 * g],     ah, bl[0], bl[1]);
                mmabf(acc[2 * g],     al, bh[0], bh[1]);
                mmabf(acc[2 * g + 1], ah, bh[2], bh[3]);
                mmabf(acc[2 * g + 1], ah, bl[2], bl[3]);
                mmabf(acc[2 * g + 1], al, bh[2], bh[3]);
            }
            {
                uint32_t b0, b1, c0, c1;
                ldsm2(b0, b1, aBh + offB2 + kadd);
                ldsm2(c0, c1, aBl + offB2 + kadd);
                mmabf(acc[4], ah, b0, b1);
                mmabf(acc[4], ah, c0, c1);
                mmabf(acc[4], al, b0, b1);
            }
        }
    }
    int gid = lane >> 2, tig = lane & 3;
    int row = bm + m0 + gid;
    #pragma unroll
    for (int nf = 0; nf < 5; nf++) {
        int col = nf * 8 + tig * 2;
        if (row < NN) {
            float2 v = make_float2(acc[nf][0] + bbo[col], acc[nf][1] + bbo[col + 1]);
            *(float2*)&out[(size_t)row * CC + col] = v;
        }
        if (row + 8 < NN) {
            float2 v = make_float2(acc[nf][2] + bbo[col], acc[nf][3] + bbo[col + 1]);
            *(float2*)&out[(size_t)(row + 8) * CC + col] = v;
        }
    }
}

// ------------------- GCN aggregation (1 node/warp) + BN column stats (fused, replicated) ---
__global__ void __launch_bounds__(256) k_gcn(int layer) {
    __shared__ float ssum[8][128];
    __shared__ float ssq[8][128];
    int tid = threadIdx.x, w = tid >> 5, l = tid & 31;
    int node = blockIdx.x * 8 + w;
    float4 rr = make_float4(0.f, 0.f, 0.f, 0.f);
    if (node < NN) {
        float dn = g_dis[node];
        float4 acc = *(const float4*)(g_h1 + (size_t)node * HH + l * 4);
        int lo = g_off[node], hi = g_off[node + 1];
        for (int e = lo; e < hi; e++) {
            int sidx = g_csr[e];
            float4 hv = *(const float4*)(g_h1 + (size_t)sidx * HH + l * 4);
            acc.x += hv.x; acc.y += hv.y; acc.z += hv.z; acc.w += hv.w;
        }
        rr = make_float4(dn * acc.x, dn * acc.y, dn * acc.z, dn * acc.w);
        *(float4*)(g_h2 + (size_t)node * HH + l * 4) = rr;
    }
    ssum[w][l * 4 + 0] = rr.x; ssum[w][l * 4 + 1] = rr.y;
    ssum[w][l * 4 + 2] = rr.z; ssum[w][l * 4 + 3] = rr.w;
    ssq[w][l * 4 + 0] = rr.x * rr.x; ssq[w][l * 4 + 1] = rr.y * rr.y;
    ssq[w][l * 4 + 2] = rr.z * rr.z; ssq[w][l * 4 + 3] = rr.w * rr.w;
    __syncthreads();
    if (tid < 128) {
        float S = 0.f, Q = 0.f;
        #pragma unroll
        for (int w2 = 0; w2 < 8; w2++) { S += ssum[w2][tid]; Q += ssq[w2][tid]; }
        int rp = blockIdx.x & (NREP - 1);
        atomicAdd(&g_sumf[layer][rp][tid], S);
        atomicAdd(&g_sqf[layer][rp][tid], Q);
    }
}

// ------------------- launch (single stream — graph-capture-safe, no statics) -------------------
extern "C" void kernel_launch(void* const* d_in, const int* in_sizes, int n_in,
                              void* d_out, int out_size) {
    const float* x      = (const float*)d_in[0];
    const void*  eidx   = d_in[1];
    const float* ln_g   = (const float*)d_in[2];
    const float* ln_b   = (const float*)d_in[3];
    const float* sw     = (const float*)d_in[4];
    const float* bw     = (const float*)d_in[5];
    const float* bb     = (const float*)d_in[6];
    // d_in[7] = gcn_bias: cancelled exactly by the following BatchNorm -> skipped
    const float* bn_g   = (const float*)d_in[8];
    const float* bn_b   = (const float*)d_in[9];
    const float* ln_go  = (const float*)d_in[10];
    const float* ln_bo  = (const float*)d_in[11];
    const float* sw_o   = (const float*)d_in[12];
    const float* bw_o   = (const float*)d_in[13];
    const float* bb_o   = (const float*)d_in[14];
    float* out = (float*)d_out;

    const int SMEM_L = 2 * 40960;   // 81920
    const int SMEM_O = 2 * 26880;   // 53760
    cudaFuncSetAttribute(k_mma_layer, cudaFuncAttributeMaxDynamicSharedMemorySize, SMEM_L);
    cudaFuncSetAttribute(k_mma_out,   cudaFuncAttributeMaxDynamicSharedMemorySize, SMEM_O);

    const int NB = (NN + 255) / 256;  // 196 scan blocks
    const int GT = (NN + 127) / 128;  // 391 M-tiles

    // init: zero counters/stats/descriptors, then fused decode|tx|prepWB0|prepWO
    k_zero_cnt<<<(NN + 255) / 256, 256>>>();
    k_mega<<<DEC_B + TX_B + PWB_B + PWO_B, 256>>>(eidx, x, sw, bw, sw_o, bw_o);

    // CSR offsets (single-pass decoupled lookback) + fill
    k_scanf<<<NB, 256>>>();
    k_fill<<<(EE + 255) / 256, 256>>>();

    for (int i = 0; i < LL; i++) {
        if (i > 0) k_prepWB<<<(640 * 128 + 255) / 256, 256>>>(sw, bw, i);
        k_mma_layer<<<GT, 256, SMEM_L>>>(bb + i * HH, ln_g + i * DD, ln_b + i * DD, i);
        k_gcn<<<(NN + 7) / 8, 256>>>(i);
        k_bnt<<<(NN + 31) / 32, 256>>>((i + 1) * 128, i + 1, i, bn_g + i * HH, bn_b + i * HH);
    }

    k_mma_out<<<GT, 256, SMEM_O>>>(bb_o, ln_go, ln_bo, out);
}

// round 16
// speedup vs baseline: 1.0359x; 1.0321x over previous
#include <cuda_runtime.h>
#include <cuda_fp16.h>
#include <cstdint>

#define NN 50000
#define NP 50048      // padded node stride for transposed tensors
#define DD 128
#define HH 128
#define CC 40
#define LL 3
#define EE 800000
#define LSTR 40       // padded SMEM row stride in bf16 units (80 bytes)
#define NREP 16       // BN stat replica buffers

// mega-kernel block ranges
#define DEC_B 3125            // decode blocks (EE/256)
#define TX_B  1563            // tx blocks (NN/32)
#define PWB_B 320             // prepWB(0) blocks (640*128/256)
#define PWO_B 400             // prepWO blocks (2560*40/256)

// ------------------- device scratch (static: no allocation) -------------------
__device__ int    g_src[EE];
__device__ int    g_dst[EE];
__device__ float  g_dis[NN];
__device__ int    g_cnt[NN];
__device__ int    g_off[NN + 1];
__device__ int    g_fill[NN];
__device__ int    g_csr[EE];
__device__ unsigned long long g_desc[256];   // decoupled-lookback descriptors
__device__ float  g_XT[(size_t)512 * NP];    // transposed raw values [d][n]
__device__ float  g_mu[4][NP];               // per-LN-set node mean
__device__ float  g_rs[4][NP];               // per-LN-set node rstd
__device__ float  g_osum[NP];                // output-LN partial: sum over 512 dims
__device__ float  g_osq[NP];                 // output-LN partial: sumsq
__device__ unsigned g_h1h[(size_t)NN * 64];  // h1 pre-scaled by dis, packed half2 [row][col/2]
__device__ float  g_h2[(size_t)NN * HH];
__device__ unsigned short g_WBh[20 * 128 * 32];   // layer B bf16-hi [chunk][n][k]
__device__ unsigned short g_WBl[20 * 128 * 32];
__device__ unsigned short g_WOh[80 * 40 * 32];    // output B bf16-hi [chunk][n][k]
__device__ unsigned short g_WOl[80 * 40 * 32];
__device__ float  g_sumf[LL][NREP][HH];      // per-layer BN column sums (replicated)
__device__ float  g_sqf[LL][NREP][HH];       // per-layer BN column sumsq

// ------------------- helpers -------------------
__device__ __forceinline__ uint32_t smem_u32(const void* p) {
    uint32_t a;
    asm("{ .reg .u64 t; cvta.to.shared.u64 t, %1; cvt.u32.u64 %0, t; }" : "=r"(a) : "l"(p));
    return a;
}
__device__ __forceinline__ uint32_t pkbf(float a, float b) {   // [bf16(a) lo16 | bf16(b) hi16]
    uint32_t r;
    asm("cvt.rn.bf16x2.f32 %0, %1, %2;" : "=r"(r) : "f"(b), "f"(a));
    return r;
}
__device__ __forceinline__ float lo2f(uint32_t v) { return __uint_as_float(v << 16); }
__device__ __forceinline__ float hi2f(uint32_t v) { return __uint_as_float(v & 0xffff0000u); }

__device__ __forceinline__ void ldsm4(uint32_t& r0, uint32_t& r1, uint32_t& r2, uint32_t& r3,
                                      uint32_t a) {
    asm volatile("ldmatrix.sync.aligned.m8n8.x4.shared.b16 {%0,%1,%2,%3}, [%4];"
                 : "=r"(r0), "=r"(r1), "=r"(r2), "=r"(r3) : "r"(a));
}
__device__ __forceinline__ void ldsm2(uint32_t& r0, uint32_t& r1, uint32_t a) {
    asm volatile("ldmatrix.sync.aligned.m8n8.x2.shared.b16 {%0,%1}, [%2];"
                 : "=r"(r0), "=r"(r1) : "r"(a));
}
__device__ __forceinline__ void mmabf(float* c, const uint32_t* a, uint32_t b0, uint32_t b1) {
    asm volatile("mma.sync.aligned.m16n8k16.row.col.f32.bf16.bf16.f32 "
                 "{%0,%1,%2,%3}, {%4,%5,%6,%7}, {%8,%9}, {%0,%1,%2,%3};"
                 : "+f"(c[0]), "+f"(c[1]), "+f"(c[2]), "+f"(c[3])
                 : "r"(a[0]), "r"(a[1]), "r"(a[2]), "r"(a[3]), "r"(b0), "r"(b1));
}
__device__ __forceinline__ void hilo2(float v0, float v1, uint32_t& h, uint32_t& l) {
    h = pkbf(v0, v1);
    l = pkbf(v0 - lo2f(h), v1 - hi2f(h));
}
__device__ __forceinline__ float silu_f(float v) {
    return __fdividef(v, 1.0f + __expf(-v));
}
__device__ __forceinline__ void bfsplit(float v, unsigned short& h, unsigned short& l) {
    asm("cvt.rn.bf16.f32 %0, %1;" : "=h"(h) : "f"(v));
    float vl = v - __uint_as_float(((uint32_t)h) << 16);
    asm("cvt.rn.bf16.f32 %0, %1;" : "=h"(l) : "f"(vl));
}
__device__ __forceinline__ float4 h2f4(uint2 u) {
    __half2 a = *(__half2*)&u.x, b = *(__half2*)&u.y;
    float2 fa = __half22float2(a), fb = __half22float2(b);
    return make_float4(fa.x, fa.y, fb.x, fb.y);
}

// ------------------- zero counters + per-layer BN stats + scan descriptors ----------------
__global__ void k_zero_cnt() {
    int i = blockIdx.x * blockDim.x + threadIdx.x;
    if (i < NN) { g_cnt[i] = 0; g_fill[i] = 0; }
    if (i < LL * NREP * HH) {
        ((float*)g_sumf)[i] = 0.f;
        ((float*)g_sqf)[i]  = 0.f;
    }
    if (i < 256) g_desc[i] = 0ull;
}

// ------------------- MEGA init kernel: decode | tx | prepWB(0) | prepWO -------------------
__global__ void __launch_bounds__(256) k_mega(const void* ep, const float* __restrict__ x,
                                              const float* __restrict__ sw,
                                              const float* __restrict__ bw,
                                              const float* __restrict__ swo,
                                              const float* __restrict__ bwo) {
    int b = blockIdx.x, t = threadIdx.x;
    if (b < DEC_B) {
        __shared__ int sflag;
        if (t == 0) {
            const unsigned* e = (const unsigned*)ep;
            int z = 0;
            #pragma unroll
            for (int i = 0; i < 16; i++) z += (e[2 * i + 1] == 0u) ? 1 : 0;
            sflag = (z == 16) ? 1 : 0;
        }
        __syncthreads();
        int i = b * 256 + t;
        if (i < EE) {
            int s, d;
            if (sflag) {
                const long long* e = (const long long*)ep;
                s = (int)e[i];
                d = (int)e[EE + i];
            } else {
                const int* e = (const int*)ep;
                s = e[i];
                d = e[EE + i];
            }
            g_src[i] = s;
            g_dst[i] = d;
            atomicAdd(&g_cnt[d], 1);
        }
    } else if (b < DEC_B + TX_B) {
        __shared__ float xs[32][129];
        int warp = t >> 5, lane = t & 31;
        int base = (b - DEC_B) * 32;
        #pragma unroll
        for (int rr = 0; rr < 4; rr++) {
            int r = warp * 4 + rr;
            int gr = base + r;
            if (gr < NN) {
                float v[4];
                float s = 0.f, sq = 0.f;
                #pragma unroll
                for (int j = 0; j < 4; j++) {
                    v[j] = x[(size_t)gr * DD + lane + j * 32];
                    s += v[j]; sq += v[j] * v[j];
                }
                #pragma unroll
                for (int o = 16; o; o >>= 1) {
                    s  += __shfl_xor_sync(0xffffffffu, s, o);
                    sq += __shfl_xor_sync(0xffffffffu, sq, o);
                }
                #pragma unroll
                for (int j = 0; j < 4; j++) xs[r][lane + j * 32] = v[j];
                if (lane == 0) {
                    float mean = s * (1.0f / 128.0f);
                    float var = sq * (1.0f / 128.0f) - mean * mean;
                    g_mu[0][gr] = mean;
                    g_rs[0][gr] = rsqrtf(var + 1e-5f);
                    g_osum[gr] = s;
                    g_osq[gr]  = sq;
                }
            }
        }
        __syncthreads();
        #pragma unroll 4
        for (int idx = t; idx < 32 * 128; idx += 256) {
            int r = idx & 31, d = idx >> 5;
            int gr = base + r;
            if (gr < NN) g_XT[(size_t)d * NP + gr] = xs[r][d];
        }
    } else if (b < DEC_B + TX_B + PWB_B) {
        int i = (b - DEC_B - TX_B) * 256 + t;
        int k = i >> 7, n = i & 127;
        float v = (k < 512) ? sw[n * 512 + k] : bw[n * 128 + (k - 512)];
        unsigned short h, l;
        bfsplit(v, h, l);
        int c = k >> 5, kl = k & 31;
        int off = (c * 128 + n) * 32 + kl;
        g_WBh[off] = h;
        g_WBl[off] = l;
    } else {
        int i = (b - DEC_B - TX_B - PWB_B) * 256 + t;
        int k = i / 40, n = i % 40;
        float v = (k < 2048) ? swo[n * 2048 + k] : bwo[n * 512 + (k - 2048)];
        unsigned short h, l;
        bfsplit(v, h, l);
        int c = k >> 5, kl = k & 31;
        int off = c * 1280 + n * 32 + kl;
        g_WOh[off] = h;
        g_WOl[off] = l;
    }
}

// ------------------- single-pass decoupled-lookback scan (+dis) -------------------
__global__ void __launch_bounds__(256) k_scanf() {
    __shared__ int ps[256];
    __shared__ int s_excl;
    int b = blockIdx.x, t = threadIdx.x, lane = t & 31;
    int i = b * 256 + t;
    int cv = (i < NN) ? g_cnt[i] : 0;
    if (i < NN) g_dis[i] = rsqrtf((float)(cv + 1));
    ps[t] = cv;
    __syncthreads();
    #pragma unroll
    for (int d = 1; d < 256; d <<= 1) {
        int u = (t >= d) ? ps[t - d] : 0;
        __syncthreads();
        ps[t] += u;
        __syncthreads();
    }
    int bsum = ps[255];
    if (t == 0)
        *((volatile unsigned long long*)&g_desc[b]) = (1ull << 32) | (unsigned)bsum;
    if (t < 32) {
        int run = 0;
        int idx = b - 1;
        while (idx >= 0) {
            int j = idx - lane;
            int f = 0, v = 0;
            if (j >= 0) {
                unsigned long long d;
                do {
                    d = *((volatile unsigned long long*)&g_desc[j]);
                    f = (int)(d >> 32);
                } while (f == 0);
                v = (int)(unsigned)d;
            }
            unsigned m = __ballot_sync(0xffffffffu, (j >= 0) && (f == 2));
            int cut = m ? (__ffs(m) - 1) : 32;
            int contrib = ((j >= 0) && (lane <= cut)) ? v : 0;
            #pragma unroll
            for (int o = 16; o; o >>= 1) contrib += __shfl_xor_sync(0xffffffffu, contrib, o);
            run += contrib;
            if (m) break;
            idx -= 32;
        }
        if (lane == 0) {
            *((volatile unsigned long long*)&g_desc[b]) = (2ull << 32) | (unsigned)(run + bsum);
            s_excl = run;
        }
    }
    __syncthreads();
    int excl = s_excl;
    if (i < NN) g_off[i] = excl + ps[t] - cv;
    if (i == NN - 1) g_off[NN] = excl + ps[t];
}

__global__ void k_fill() {
    int i = blockIdx.x * blockDim.x + threadIdx.x;
    if (i >= EE) return;
    int d = g_dst[i];
    int p = g_off[d] + atomicAdd(&g_fill[d], 1);
    g_csr[p] = g_src[i];
}

// ------------------- BN finalize(+apply) + transpose into XT + next-LN stats + out-LN partials
__global__ void __launch_bounds__(256) k_bnt(int rowBase, int statSet, int layer,
                                             const float* __restrict__ bng,
                                             const float* __restrict__ bnb) {
    __shared__ float xs[32][129];
    __shared__ float s_sc[128], s_of[128];
    int tid = threadIdx.x;
    int warp = tid >> 5, lane = tid & 31;
    int base = blockIdx.x * 32;
    if (tid < 128) {
        float S = 0.f, Q = 0.f;
        #pragma unroll
        for (int rp = 0; rp < NREP; rp++) { S += g_sumf[layer][rp][tid]; Q += g_sqf[layer][rp][tid]; }
        float m = S * (1.0f / NN);
        float var = Q * (1.0f / NN) - m * m;
        float sc = bng[tid] * rsqrtf(var + 1e-5f);
        s_sc[tid] = sc;
        s_of[tid] = bnb[tid] - m * sc;
    }
    __syncthreads();
    #pragma unroll
    for (int rr = 0; rr < 4; rr++) {
        int r = warp * 4 + rr;
        int gr = base + r;
        if (gr < NN) {
            float v[4];
            float s = 0.f, sq = 0.f;
            #pragma unroll
            for (int j = 0; j < 4; j++) {
                int c = lane + j * 32;
                v[j] = g_h2[(size_t)gr * HH + c] * s_sc[c] + s_of[c];
                s += v[j]; sq += v[j] * v[j];
            }
            #pragma unroll
            for (int o = 16; o; o >>= 1) {
                s  += __shfl_xor_sync(0xffffffffu, s, o);
                sq += __shfl_xor_sync(0xffffffffu, sq, o);
            }
            #pragma unroll
            for (int j = 0; j < 4; j++) xs[r][lane + j * 32] = v[j];
            if (lane == 0) {
                float mean = s * (1.0f / 128.0f);
                float var = sq * (1.0f / 128.0f) - mean * mean;
                g_mu[statSet][gr] = mean;
                g_rs[statSet][gr] = rsqrtf(var + 1e-5f);
                g_osum[gr] += s;
                g_osq[gr]  += sq;
            }
        }
    }
    __syncthreads();
    #pragma unroll 4
    for (int idx = tid; idx < 32 * 128; idx += 256) {
        int r = idx & 31, d = idx >> 5;
        int gr = base + r;
        if (gr < NN) g_XT[(size_t)(rowBase + d) * NP + gr] = xs[r][d];
    }
}

// ------------------- weight prep (layers 1,2) -------------------
__global__ void k_prepWB(const float* __restrict__ sw, const float* __restrict__ bw, int li) {
    int i = blockIdx.x * blockDim.x + threadIdx.x;
    if (i >= 640 * 128) return;
    int k = i >> 7, n = i & 127;
    sw += (size_t)li * 128 * 512;
    bw += (size_t)li * 128 * 128;
    float v = (k < 512) ? sw[n * 512 + k] : bw[n * 128 + (k - 512)];
    unsigned short h, l;
    bfsplit(v, h, l);
    int c = k >> 5, kl = k & 31;
    int off = (c * 128 + n) * 32 + kl;
    g_WBh[off] = h;
    g_WBl[off] = l;
}

// ------------------- A-chunk stores: LN+RBF or SiLU applied to prefetched raw values -----
__device__ __forceinline__ void store_basis(char* aAh, char* aAl, const float* pv,
                                            int r, int kh, float mu, float rs,
                                            const float* lg, const float* lb) {
    #pragma unroll
    for (int jp = 0; jp < 2; jp++) {
        uint32_t hv[4], lv[4];
        #pragma unroll
        for (int dd = 0; dd < 2; dd++) {
            int j = jp * 2 + dd;
            float xn = (pv[j] - mu) * rs * lg[j] + lb[j];
            float z0 = (xn + 2.0f) * 0.75f;
            float z1 = (xn + 0.66666667f) * 0.75f;
            float z2 = (xn - 0.66666667f) * 0.75f;
            float z3 = (xn - 2.0f) * 0.75f;
            float e0 = __expf(-z0 * z0), e1 = __expf(-z1 * z1);
            float e2 = __expf(-z2 * z2), e3 = __expf(-z3 * z3);
            hilo2(e0, e1, hv[dd * 2 + 0], lv[dd * 2 + 0]);
            hilo2(e2, e3, hv[dd * 2 + 1], lv[dd * 2 + 1]);
        }
        int kb = kh * 16 + jp * 8;
        *(uint4*)(aAh + (r * LSTR + kb) * 2) = make_uint4(hv[0], hv[1], hv[2], hv[3]);
        *(uint4*)(aAl + (r * LSTR + kb) * 2) = make_uint4(lv[0], lv[1], lv[2], lv[3]);
    }
}
__device__ __forceinline__ void store_silu(char* aAh, char* aAl, const float* pv, int r, int kh) {
    #pragma unroll
    for (int q = 0; q < 2; q++) {
        uint32_t hv[4], lv[4];
        #pragma unroll
        for (int p = 0; p < 4; p++) {
            float a = silu_f(pv[q * 8 + 2 * p]);
            float b = silu_f(pv[q * 8 + 2 * p + 1]);
            hilo2(a, b, hv[p], lv[p]);
        }
        int kb = kh * 16 + q * 8;
        *(uint4*)(aAh + (r * LSTR + kb) * 2) = make_uint4(hv[0], hv[1], hv[2], hv[3]);
        *(uint4*)(aAl + (r * LSTR + kb) * 2) = make_uint4(lv[0], lv[1], lv[2], lv[3]);
    }
}

// ------------------- layer GEMM (pipelined, 2 blocks/SM): h1h = half(dis*(A@W^T + bb)) ----
__global__ void __launch_bounds__(256, 2) k_mma_layer(const float* __restrict__ bb,
                                                      const float* __restrict__ lng,
                                                      const float* __restrict__ lnb,
                                                      int set) {
    extern __shared__ char sm[];
    __shared__ float s_lg[128], s_lb[128];
    const int BUF = 40960;   // Ah 10240 | Al 10240 | Bh 10240 | Bl 10240
    int tid = threadIdx.x, lane = tid & 31, w = tid >> 5;
    int bm = blockIdx.x * 128;
    int r = tid & 127, kh = tid >> 7;
    int m0 = (w & 3) * 32, n0 = (w >> 2) * 64;
    int rb = set * 128;

    if (tid < 128) { s_lg[tid] = lng[tid]; s_lb[tid] = lnb[tid]; }
    float mu = g_mu[set][bm + r];
    float rs = g_rs[set][bm + r];

    float acc[2][8][4];
    #pragma unroll
    for (int a = 0; a < 2; a++)
        #pragma unroll
        for (int b = 0; b < 8; b++)
            #pragma unroll
            for (int c = 0; c < 4; c++) acc[a][b][c] = 0.f;

    uint32_t sb = smem_u32(sm);
    uint32_t offA = ((m0 + (lane & 15)) * LSTR + (lane >> 4) * 8) * 2;
    uint32_t offB = ((n0 + (lane & 7) + ((lane & 16) ? 8 : 0)) * LSTR + ((lane >> 3) & 1) * 8) * 2;

    float pv[16];
    uint4 pbh[2], pbl[2];
    {
        int d0 = rb + kh * 4;
        #pragma unroll
        for (int j = 0; j < 4; j++) pv[j] = g_XT[(size_t)(d0 + j) * NP + bm + r];
        const uint4* sh = (const uint4*)g_WBh;
        const uint4* sl = (const uint4*)g_WBl;
        pbh[0] = sh[tid]; pbh[1] = sh[tid + 256];
        pbl[0] = sl[tid]; pbl[1] = sl[tid + 256];
    }
    __syncthreads();   // s_lg/s_lb ready

    for (int c = 0; c < 20; c++) {
        int cur = c & 1;
        char* base = sm + cur * BUF;
        if (c < 16) store_basis(base, base + 10240, pv, r, kh, mu, rs,
                                &s_lg[c * 8 + kh * 4], &s_lb[c * 8 + kh * 4]);
        else        store_silu (base, base + 10240, pv, r, kh);
        {
            int n = tid >> 2, kq = tid & 3;
            int i2 = tid + 256;
            int n2 = i2 >> 2, kq2 = i2 & 3;
            *(uint4*)(base + 20480 + (n * LSTR + kq * 8) * 2)  = pbh[0];
            *(uint4*)(base + 20480 + (n2 * LSTR + kq2 * 8) * 2) = pbh[1];
            *(uint4*)(base + 30720 + (n * LSTR + kq * 8) * 2)  = pbl[0];
            *(uint4*)(base + 30720 + (n2 * LSTR + kq2 * 8) * 2) = pbl[1];
        }
        __syncthreads();
        if (c < 19) {
            int cn = c + 1;
            if (cn < 16) {
                int d0 = rb + cn * 8 + kh * 4;
                #pragma unroll
                for (int j = 0; j < 4; j++) pv[j] = g_XT[(size_t)(d0 + j) * NP + bm + r];
            } else {
                int sd0 = rb + (cn - 16) * 32 + kh * 16;
                #pragma unroll
                for (int q = 0; q < 16; q++) pv[q] = g_XT[(size_t)(sd0 + q) * NP + bm + r];
            }
            const uint4* sh = (const uint4*)g_WBh + cn * 512;
            const uint4* sl = (const uint4*)g_WBl + cn * 512;
            pbh[0] = sh[tid]; pbh[1] = sh[tid + 256];
            pbl[0] = sl[tid]; pbl[1] = sl[tid + 256];
        }
        uint32_t aAh = sb + cur * BUF, aAl = aAh + 10240;
        uint32_t aBh = aAh + 20480,   aBl = aAh + 30720;
        #pragma unroll
        for (int ks = 0; ks < 2; ks++) {
            uint32_t kadd = ks * 32;
            uint32_t ah[2][4], al[2][4];
            ldsm4(ah[0][0], ah[0][1], ah[0][2], ah[0][3], aAh + offA + kadd);
            ldsm4(ah[1][0], ah[1][1], ah[1][2], ah[1][3], aAh + offA + kadd + 16 * LSTR * 2);
            ldsm4(al[0][0], al[0][1], al[0][2], al[0][3], aAl + offA + kadd);
            ldsm4(al[1][0], al[1][1], al[1][2], al[1][3], aAl + offA + kadd + 16 * LSTR * 2);
            #pragma unroll
            for (int p = 0; p < 4; p++) {
                uint32_t bh[4], bl[4];
                uint32_t po = (uint32_t)(p * 16 * LSTR * 2);
                ldsm4(bh[0], bh[1], bh[2], bh[3], aBh + offB + kadd + po);
                ldsm4(bl[0], bl[1], bl[2], bl[3], aBl + offB + kadd + po);
                #pragma unroll
                for (int mf = 0; mf < 2; mf++) {
                    mmabf(acc[mf][2 * p],     ah[mf], bh[0], bh[1]);
                    mmabf(acc[mf][2 * p],     ah[mf], bl[0], bl[1]);
                    mmabf(acc[mf][2 * p],     al[mf], bh[0], bh[1]);
                    mmabf(acc[mf][2 * p + 1], ah[mf], bh[2], bh[3]);
                    mmabf(acc[mf][2 * p + 1], ah[mf], bl[2], bl[3]);
                    mmabf(acc[mf][2 * p + 1], al[mf], bh[2], bh[3]);
                }
            }
        }
    }
    int gid = lane >> 2, tig = lane & 3;
    #pragma unroll
    for (int mf = 0; mf < 2; mf++) {
        int row = bm + m0 + mf * 16 + gid;
        float d0 = (row < NN) ? g_dis[row] : 0.f;
        float d1 = (row + 8 < NN) ? g_dis[row + 8] : 0.f;
        #pragma unroll
        for (int nf = 0; nf < 8; nf++) {
            int col = n0 + nf * 8 + tig * 2;
            if (row < NN) {
                __half2 hv = __floats2half2_rn((acc[mf][nf][0] + bb[col]) * d0,
                                               (acc[mf][nf][1] + bb[col + 1]) * d0);
                g_h1h[(size_t)row * 64 + (col >> 1)] = *(unsigned*)&hv;
            }
            if (row + 8 < NN) {
                __half2 hv = __floats2half2_rn((acc[mf][nf][2] + bb[col]) * d1,
                                               (acc[mf][nf][3] + bb[col + 1]) * d1);
                g_h1h[(size_t)(row + 8) * 64 + (col >> 1)] = *(unsigned*)&hv;
            }
        }
    }
}

// ------------------- output GEMM (pipelined, N=40, 2 blocks/SM) -------------------
__global__ void __launch_bounds__(256, 2) k_mma_out(const float* __restrict__ bbo,
                                                    const float* __restrict__ lng,
                                                    const float* __restrict__ lnb,
                                                    float* __restrict__ out) {
    extern __shared__ char sm[];
    __shared__ float s_lg[512], s_lb[512];
    const int BUF = 26880;   // Ah 10240 | Al 10240 | Bh 3200 | Bl 3200
    int tid = threadIdx.x, lane = tid & 31, w = tid >> 5;
    int bm = blockIdx.x * 128;
    int r = tid & 127, kh = tid >> 7;
    int m0 = w * 16;

    #pragma unroll
    for (int i = tid; i < 512; i += 256) { s_lg[i] = lng[i]; s_lb[i] = lnb[i]; }
    float mu, rs;
    {
        float s = g_osum[bm + r], sq = g_osq[bm + r];
        mu = s * (1.0f / 512.0f);
        float var = sq * (1.0f / 512.0f) - mu * mu;
        rs = rsqrtf(var + 1e-5f);
    }

    float acc[5][4];
    #pragma unroll
    for (int b = 0; b < 5; b++)
        #pragma unroll
        for (int c = 0; c < 4; c++) acc[b][c] = 0.f;

    uint32_t sb = smem_u32(sm);
    uint32_t offA  = ((m0 + (lane & 15)) * LSTR + (lane >> 4) * 8) * 2;
    uint32_t offB  = (((lane & 7) + ((lane & 16) ? 8 : 0)) * LSTR + ((lane >> 3) & 1) * 8) * 2;
    uint32_t offB2 = ((32 + (lane & 7)) * LSTR + ((lane >> 3) & 1) * 8) * 2;

    float pv[16];
    uint4 pbh, pbl;
    {
        int d0 = kh * 4;
        #pragma unroll
        for (int j = 0; j < 4; j++) pv[j] = g_XT[(size_t)(d0 + j) * NP + bm + r];
        if (tid < 160) {
            pbh = ((const uint4*)g_WOh)[tid];
            pbl = ((const uint4*)g_WOl)[tid];
        }
    }
    __syncthreads();   // s_lg/s_lb ready

    for (int c = 0; c < 80; c++) {
        int cur = c & 1;
        char* base = sm + cur * BUF;
        if (c < 64) store_basis(base, base + 10240, pv, r, kh, mu, rs,
                                &s_lg[c * 8 + kh * 4], &s_lb[c * 8 + kh * 4]);
        else        store_silu (base, base + 10240, pv, r, kh);
        if (tid < 160) {
            int n = tid >> 2, kq = tid & 3;
            *(uint4*)(base + 20480 + (n * LSTR + kq * 8) * 2) = pbh;
            *(uint4*)(base + 23680 + (n * LSTR + kq * 8) * 2) = pbl;
        }
        __syncthreads();
        if (c < 79) {
            int cn = c + 1;
            if (cn < 64) {
                int d0 = cn * 8 + kh * 4;
                #pragma unroll
                for (int j = 0; j < 4; j++) pv[j] = g_XT[(size_t)(d0 + j) * NP + bm + r];
            } else {
                int sd0 = (cn - 64) * 32 + kh * 16;
                #pragma unroll
                for (int q = 0; q < 16; q++) pv[q] = g_XT[(size_t)(sd0 + q) * NP + bm + r];
            }
            if (tid < 160) {
                pbh = ((const uint4*)g_WOh + cn * 160)[tid];
                pbl = ((const uint4*)g_WOl + cn * 160)[tid];
            }
        }
        uint32_t aAh = sb + cur * BUF, aAl = aAh + 10240;
        uint32_t aBh = aAh + 20480,   aBl = aAh + 23680;
        #pragma unroll
        for (int ks = 0; ks < 2; ks++) {
            uint32_t kadd = ks * 32;
            uint32_t ah[4], al[4];
            ldsm4(ah[0], ah[1], ah[2], ah[3], aAh + offA + kadd);
            ldsm4(al[0], al[1], al[2], al[3], aAl + offA + kadd);
            #pragma unroll
            for (int g = 0; g < 2; g++) {
                uint32_t bh[4], bl[4];
                uint32_t po = (uint32_t)(g * 16 * LSTR * 2);
                ldsm4(bh[0], bh[1], bh[2], bh[3], aBh + offB + kadd + po);
                ldsm4(bl[0], bl[1], bl[2], bl[3], aBl + offB + kadd + po);
                mmabf(acc[2 * g],     ah, bh[0], bh[1]);
                mmabf(acc[2 * g],     ah, bl[0], bl[1]);
                mmabf(acc[2 * g],     al, bh[0], bh[1]);
                mmabf(acc[2 * g + 1], ah, bh[2], bh[3]);
                mmabf(acc[2 * g + 1], ah, bl[2], bl[3]);
                mmabf(acc[2 * g + 1], al, bh[2], bh[3]);
            }
            {
                uint32_t b0, b1, c0, c1;
                ldsm2(b0, b1, aBh + offB2 + kadd);
                ldsm2(c0, c1, aBl + offB2 + kadd);
                mmabf(acc[4], ah, b0, b1);
                mmabf(acc[4], ah, c0, c1);
                mmabf(acc[4], al, b0, b1);
            }
        }
    }
    int gid = lane >> 2, tig = lane & 3;
    int row = bm + m0 + gid;
    #pragma unroll
    for (int nf = 0; nf < 5; nf++) {
        int col = nf * 8 + tig * 2;
        if (row < NN) {
            float2 v = make_float2(acc[nf][0] + bbo[col], acc[nf][1] + bbo[col + 1]);
            *(float2*)&out[(size_t)row * CC + col] = v;
        }
        if (row + 8 < NN) {
            float2 v = make_float2(acc[nf][2] + bbo[col], acc[nf][3] + bbo[col + 1]);
            *(float2*)&out[(size_t)(row + 8) * CC + col] = v;
        }
    }
}

// ------------------- GCN aggregation (1 node/warp, fp16 gather) + BN stats ----------------
__global__ void __launch_bounds__(256) k_gcn(int layer) {
    __shared__ float ssum[8][128];
    __shared__ float ssq[8][128];
    int tid = threadIdx.x, w = tid >> 5, l = tid & 31;
    int node = blockIdx.x * 8 + w;
    float4 rr = make_float4(0.f, 0.f, 0.f, 0.f);
    if (node < NN) {
        float dn = g_dis[node];
        const uint2* H = (const uint2*)g_h1h;
        float4 acc = h2f4(H[(size_t)node * 32 + l]);   // self term
        int lo = g_off[node], hi = g_off[node + 1];
        for (int e = lo; e < hi; e++) {
            int sidx = g_csr[e];
            float4 hv = h2f4(H[(size_t)sidx * 32 + l]);
            acc.x += hv.x; acc.y += hv.y; acc.z += hv.z; acc.w += hv.w;
        }
        rr = make_float4(dn * acc.x, dn * acc.y, dn * acc.z, dn * acc.w);
        *(float4*)(g_h2 + (size_t)node * HH + l * 4) = rr;
    }
    ssum[w][l * 4 + 0] = rr.x; ssum[w][l * 4 + 1] = rr.y;
    ssum[w][l * 4 + 2] = rr.z; ssum[w][l * 4 + 3] = rr.w;
    ssq[w][l * 4 + 0] = rr.x * rr.x; ssq[w][l * 4 + 1] = rr.y * rr.y;
    ssq[w][l * 4 + 2] = rr.z * rr.z; ssq[w][l * 4 + 3] = rr.w * rr.w;
    __syncthreads();
    if (tid < 128) {
        float S = 0.f, Q = 0.f;
        #pragma unroll
        for (int w2 = 0; w2 < 8; w2++) { S += ssum[w2][tid]; Q += ssq[w2][tid]; }
        int rp = blockIdx.x & (NREP - 1);
        atomicAdd(&g_sumf[layer][rp][tid], S);
        atomicAdd(&g_sqf[layer][rp][tid], Q);
    }
}

// ------------------- launch (single stream — graph-capture-safe, no statics) -------------------
extern "C" void kernel_launch(void* const* d_in, const int* in_sizes, int n_in,
                              void* d_out, int out_size) {
    const float* x      = (const float*)d_in[0];
    const void*  eidx   = d_in[1];
    const float* ln_g   = (const float*)d_in[2];
    const float* ln_b   = (const float*)d_in[3];
    const float* sw     = (const float*)d_in[4];
    const float* bw     = (const float*)d_in[5];
    const float* bb     = (const float*)d_in[6];
    // d_in[7] = gcn_bias: cancelled exactly by the following BatchNorm -> skipped
    const float* bn_g   = (const float*)d_in[8];
    const float* bn_b   = (const float*)d_in[9];
    const float* ln_go  = (const float*)d_in[10];
    const float* ln_bo  = (const float*)d_in[11];
    const float* sw_o   = (const float*)d_in[12];
    const float* bw_o   = (const float*)d_in[13];
    const float* bb_o   = (const float*)d_in[14];
    float* out = (float*)d_out;

    const int SMEM_L = 2 * 40960;   // 81920
    const int SMEM_O = 2 * 26880;   // 53760
    cudaFuncSetAttribute(k_mma_layer, cudaFuncAttributeMaxDynamicSharedMemorySize, SMEM_L);
    cudaFuncSetAttribute(k_mma_out,   cudaFuncAttributeMaxDynamicSharedMemorySize, SMEM_O);

    const int NB = (NN + 255) / 256;  // 196 scan blocks
    const int GT = (NN + 127) / 128;  // 391 M-tiles

    // init: zero counters/stats/descriptors, then fused decode|tx|prepWB0|prepWO
    k_zero_cnt<<<(NN + 255) / 256, 256>>>();
    k_mega<<<DEC_B + TX_B + PWB_B + PWO_B, 256>>>(eidx, x, sw, bw, sw_o, bw_o);

    // CSR offsets (single-pass decoupled lookback) + fill
    k_scanf<<<NB, 256>>>();
    k_fill<<<(EE + 255) / 256, 256>>>();

    for (int i = 0; i < LL; i++) {
        if (i > 0) k_prepWB<<<(640 * 128 + 255) / 256, 256>>>(sw, bw, i);
        k_mma_layer<<<GT, 256, SMEM_L>>>(bb + i * HH, ln_g + i * DD, ln_b + i * DD, i);
        k_gcn<<<(NN + 7) / 8, 256>>>(i);
        k_bnt<<<(NN + 31) / 32, 256>>>((i + 1) * 128, i + 1, i, bn_g + i * HH, bn_b + i * HH);
    }

    k_mma_out<<<GT, 256, SMEM_O>>>(bb_o, ln_go, ln_bo, out);
}